// round 1
// baseline (speedup 1.0000x reference)
#include <cuda_runtime.h>
#include <cuda_bf16.h>
#include <math_constants.h>

#define DIM 2048
#define N_HEADS 16
#define N_KV_HEADS 4
#define HEAD_DIM 128
#define BB 2
#define SS 2048
#define ROWS (BB*SS)              // 4096
#define KV_DIM (N_KV_HEADS*HEAD_DIM)  // 512

// ---------------- static scratch (no allocations allowed) ----------------
__device__ float g_Q[(size_t)ROWS * DIM];     // 32 MB
__device__ float g_K[(size_t)ROWS * KV_DIM];  // 8 MB
__device__ float g_V[(size_t)ROWS * KV_DIM];  // 8 MB
__device__ float g_O[(size_t)ROWS * DIM];     // 32 MB

// ---------------- classic 128x128x8 register-tiled SGEMM ----------------
// C[M,N] = A[M,K] * B[K,N], row-major, all dims multiples of tile sizes.
__global__ __launch_bounds__(256) void sgemm_kernel(
    const float* __restrict__ A, const float* __restrict__ B,
    float* __restrict__ C, int M, int N, int K)
{
    constexpr int BM = 128, BN = 128, BK = 8, TM = 8, TN = 8;
    __shared__ float As[BK][BM];
    __shared__ float Bs[BK][BN];

    const int tid = threadIdx.x;
    const int bm = blockIdx.y * BM;
    const int bn = blockIdx.x * BN;
    const int tx = tid % 16;          // 16 x 16 thread grid
    const int ty = tid / 16;

    // A loads: 128x8 floats -> one float4 along K per thread
    const int arow = tid >> 1;              // 0..127
    const int acol = (tid & 1) * 4;         // 0 or 4
    // B loads: 8x128 floats -> one float4 along N per thread
    const int brow = tid >> 5;              // 0..7
    const int bcol = (tid & 31) * 4;

    float acc[TM][TN];
    #pragma unroll
    for (int i = 0; i < TM; i++)
        #pragma unroll
        for (int j = 0; j < TN; j++) acc[i][j] = 0.f;

    for (int k0 = 0; k0 < K; k0 += BK) {
        float4 av = *(const float4*)&A[(size_t)(bm + arow) * K + k0 + acol];
        As[acol + 0][arow] = av.x;
        As[acol + 1][arow] = av.y;
        As[acol + 2][arow] = av.z;
        As[acol + 3][arow] = av.w;
        *(float4*)&Bs[brow][bcol] =
            *(const float4*)&B[(size_t)(k0 + brow) * N + bn + bcol];
        __syncthreads();

        #pragma unroll
        for (int kk = 0; kk < BK; kk++) {
            float a[TM], b[TN];
            #pragma unroll
            for (int i = 0; i < TM; i++) a[i] = As[kk][ty * TM + i];
            #pragma unroll
            for (int j = 0; j < TN; j++) b[j] = Bs[kk][tx * TN + j];
            #pragma unroll
            for (int i = 0; i < TM; i++)
                #pragma unroll
                for (int j = 0; j < TN; j++)
                    acc[i][j] = fmaf(a[i], b[j], acc[i][j]);
        }
        __syncthreads();
    }

    #pragma unroll
    for (int i = 0; i < TM; i++)
        #pragma unroll
        for (int j = 0; j < TN; j += 4) {
            float4 v = make_float4(acc[i][j], acc[i][j+1], acc[i][j+2], acc[i][j+3]);
            *(float4*)&C[(size_t)(bm + ty * TM + i) * N + bn + tx * TN + j] = v;
        }
}

// ---------------- RoPE (interleaved pairs) ----------------
// layout: [b][s][h][d], d pairs (2*i, 2*i+1)
__global__ void rope_kernel(float* __restrict__ q,
                            const float* __restrict__ cosb,
                            const float* __restrict__ sinb,
                            int n_heads, int total)
{
    int idx = blockIdx.x * blockDim.x + threadIdx.x;
    if (idx >= total) return;
    int d2  = idx & 63;                       // HEAD_DIM/2 = 64
    int row = idx >> 6;                       // (b*S + s)*n_heads + h
    int s   = (row / n_heads) % SS;
    float c  = cosb[s * 64 + d2];
    float sn = sinb[s * 64 + d2];
    float* p = q + (size_t)row * HEAD_DIM + 2 * d2;
    float r = p[0], i = p[1];
    p[0] = r * c - i * sn;
    p[1] = r * sn + i * c;
}

// ---------------- causal GQA attention, online softmax ----------------
// grid: (S/32, N_HEADS, B). block: 1024 threads (32 warps), warp w owns
// query row s = tile*32 + w. K/V streamed through smem in 64-key tiles.
__global__ __launch_bounds__(1024) void attn_kernel(
    const float* __restrict__ Q, const float* __restrict__ K,
    const float* __restrict__ V, float* __restrict__ O)
{
    extern __shared__ float sm[];
    float* Ks = sm;                 // 64*128
    float* Vs = sm + 64 * 128;      // 64*128

    const int b    = blockIdx.z;
    const int h    = blockIdx.y;
    const int tile = blockIdx.x;
    const int kh   = h / (N_HEADS / N_KV_HEADS);
    const int warp = threadIdx.x >> 5;
    const int lane = threadIdx.x & 31;
    const int s    = tile * 32 + warp;
    const float scale = 0.08838834764831845f;   // 1/sqrt(128)

    const float4 qv = *(const float4*)&Q[((size_t)(b * SS + s) * N_HEADS + h) * HEAD_DIM + lane * 4];

    float m = -CUDART_INF_F, l = 0.f;
    float4 acc = make_float4(0.f, 0.f, 0.f, 0.f);

    const int smax   = tile * 32 + 31;
    const int ntiles = smax / 64 + 1;

    for (int jt = 0; jt < ntiles; jt++) {
        const int t0 = jt * 64;
        // cooperative K/V tile load: 64 keys x 128 dims, float4 granularity
        for (int i = threadIdx.x; i < 64 * 32; i += 1024) {
            int row = i >> 5, c4 = i & 31;
            size_t src = ((size_t)(b * SS + t0 + row) * N_KV_HEADS + kh) * HEAD_DIM + c4 * 4;
            *(float4*)&Ks[row * 128 + c4 * 4] = *(const float4*)&K[src];
            *(float4*)&Vs[row * 128 + c4 * 4] = *(const float4*)&V[src];
        }
        __syncthreads();

        const int jmax = min(63, s - t0);
        #pragma unroll 4
        for (int j = 0; j <= jmax; j++) {
            float4 kv = *(const float4*)&Ks[j * 128 + lane * 4];
            float x = qv.x * kv.x + qv.y * kv.y + qv.z * kv.z + qv.w * kv.w;
            #pragma unroll
            for (int o = 16; o; o >>= 1) x += __shfl_xor_sync(0xffffffffu, x, o);
            x *= scale;
            float mnew = fmaxf(m, x);
            float corr = __expf(m - mnew);
            float p    = __expf(x - mnew);
            l = l * corr + p;
            float4 vv = *(const float4*)&Vs[j * 128 + lane * 4];
            acc.x = acc.x * corr + p * vv.x;
            acc.y = acc.y * corr + p * vv.y;
            acc.z = acc.z * corr + p * vv.z;
            acc.w = acc.w * corr + p * vv.w;
            m = mnew;
        }
        __syncthreads();
    }

    const float inv = 1.f / l;
    float4 o4 = make_float4(acc.x * inv, acc.y * inv, acc.z * inv, acc.w * inv);
    *(float4*)&O[((size_t)(b * SS + s) * N_HEADS + h) * HEAD_DIM + lane * 4] = o4;
}

// ---------------- launch ----------------
extern "C" void kernel_launch(void* const* d_in, const int* in_sizes, int n_in,
                              void* d_out, int out_size)
{
    const float* x    = (const float*)d_in[0];
    const float* fcos = (const float*)d_in[1];
    const float* fsin = (const float*)d_in[2];
    const float* wq   = (const float*)d_in[3];
    const float* wk   = (const float*)d_in[4];
    const float* wv   = (const float*)d_in[5];
    const float* wo   = (const float*)d_in[6];
    float* out = (float*)d_out;

    float *Q, *K, *V, *O;
    cudaGetSymbolAddress((void**)&Q, g_Q);
    cudaGetSymbolAddress((void**)&K, g_K);
    cudaGetSymbolAddress((void**)&V, g_V);
    cudaGetSymbolAddress((void**)&O, g_O);

    // QKV projections
    sgemm_kernel<<<dim3(DIM / 128, ROWS / 128), 256>>>(x, wq, Q, ROWS, DIM, DIM);
    sgemm_kernel<<<dim3(KV_DIM / 128, ROWS / 128), 256>>>(x, wk, K, ROWS, KV_DIM, DIM);
    sgemm_kernel<<<dim3(KV_DIM / 128, ROWS / 128), 256>>>(x, wv, V, ROWS, KV_DIM, DIM);

    // RoPE on Q and K
    {
        int totQ = BB * SS * N_HEADS * (HEAD_DIM / 2);
        int totK = BB * SS * N_KV_HEADS * (HEAD_DIM / 2);
        rope_kernel<<<(totQ + 255) / 256, 256>>>(Q, fcos, fsin, N_HEADS, totQ);
        rope_kernel<<<(totK + 255) / 256, 256>>>(K, fcos, fsin, N_KV_HEADS, totK);
    }

    // attention
    {
        int smem = 2 * 64 * 128 * sizeof(float);   // 64 KB
        cudaFuncSetAttribute(attn_kernel, cudaFuncAttributeMaxDynamicSharedMemorySize, smem);
        attn_kernel<<<dim3(SS / 32, N_HEADS, BB), 1024, smem>>>(Q, K, V, O);
    }

    // output projection
    sgemm_kernel<<<dim3(DIM / 128, ROWS / 128), 256>>>(O, wo, out, ROWS, DIM, DIM);
}

// round 2
// speedup vs baseline: 1.3227x; 1.3227x over previous
#include <cuda_runtime.h>
#include <cuda_bf16.h>
#include <math_constants.h>
#include <cstdint>

#define DIM 2048
#define N_HEADS 16
#define N_KV_HEADS 4
#define HEAD_DIM 128
#define BB 2
#define SS 2048
#define ROWS (BB*SS)              // 4096
#define KV_DIM (N_KV_HEADS*HEAD_DIM)  // 512

// ---------------- static scratch (no allocations allowed) ----------------
__device__ float g_Q[(size_t)ROWS * DIM];     // 32 MB
__device__ float g_K[(size_t)ROWS * KV_DIM];  // 8 MB
__device__ float g_V[(size_t)ROWS * KV_DIM];  // 8 MB
__device__ float g_O[(size_t)ROWS * DIM];     // 32 MB

// ---------------- tf32 helpers ----------------
__device__ __forceinline__ uint32_t f2tf32(float x) {
    uint32_t r;
    asm("cvt.rna.tf32.f32 %0, %1;" : "=r"(r) : "f"(x));
    return r;
}

__device__ __forceinline__ void mma_tf32(float& d0, float& d1, float& d2, float& d3,
                                         uint32_t a0, uint32_t a1, uint32_t a2, uint32_t a3,
                                         uint32_t b0, uint32_t b1) {
    asm volatile(
        "mma.sync.aligned.m16n8k8.row.col.f32.tf32.tf32.f32 "
        "{%0,%1,%2,%3}, {%4,%5,%6,%7}, {%8,%9}, {%0,%1,%2,%3};\n"
        : "+f"(d0), "+f"(d1), "+f"(d2), "+f"(d3)
        : "r"(a0), "r"(a1), "r"(a2), "r"(a3), "r"(b0), "r"(b1));
}

// ---------------- tf32 tensor-core GEMM ----------------
// C[M,N] = A[M,K] * B[K,N], row-major. M%128==0, N%128==0, K%16==0.
// Block 128x128x16, 256 threads (8 warps, 2x4), warp tile 64x32 (m16n8k8).
__global__ __launch_bounds__(256) void tf32_gemm(
    const float* __restrict__ A, const float* __restrict__ B,
    float* __restrict__ C, int M, int N, int K)
{
    constexpr int BM = 128, BN = 128, BK = 16;
    constexpr int ASTR = BK + 4;   // 20 floats: conflict-free frag loads, 16B aligned
    constexpr int BSTR = BN + 4;   // 132 floats

    __shared__ uint32_t As[BM * ASTR];   // [m][k]
    __shared__ uint32_t Bs[BK * BSTR];   // [k][n]

    const int tid  = threadIdx.x;
    const int warp = tid >> 5;
    const int lane = tid & 31;
    const int g    = lane >> 2;      // group id 0..7
    const int c    = lane & 3;       // thread in group 0..3

    const int wm = (warp & 1) * 64;      // warp row offset in tile
    const int wn = (warp >> 1) * 32;     // warp col offset in tile

    const int bm = blockIdx.y * BM;
    const int bn = blockIdx.x * BN;

    // global load mapping
    const int ar = tid >> 1;             // A row 0..127
    const int ak = (tid & 1) * 8;        // A k-offset 0 or 8
    const int br = tid >> 4;             // B k-row 0..15
    const int bc = (tid & 15) * 8;       // B col offset

    const float* Ag = A + (size_t)(bm + ar) * K + ak;
    const float* Bg = B + (size_t)br * N + bn + bc;

    float4 pa0, pa1, pb0, pb1;
    pa0 = *(const float4*)(Ag);
    pa1 = *(const float4*)(Ag + 4);
    pb0 = *(const float4*)(Bg);
    pb1 = *(const float4*)(Bg + 4);

    float acc[4][4][4];
    #pragma unroll
    for (int i = 0; i < 4; i++)
        #pragma unroll
        for (int j = 0; j < 4; j++)
            #pragma unroll
            for (int r = 0; r < 4; r++) acc[i][j][r] = 0.f;

    for (int k0 = 0; k0 < K; k0 += BK) {
        // stash prefetched tile to smem (converted to tf32)
        {
            uint4 v;
            v.x = f2tf32(pa0.x); v.y = f2tf32(pa0.y); v.z = f2tf32(pa0.z); v.w = f2tf32(pa0.w);
            *(uint4*)&As[ar * ASTR + ak] = v;
            v.x = f2tf32(pa1.x); v.y = f2tf32(pa1.y); v.z = f2tf32(pa1.z); v.w = f2tf32(pa1.w);
            *(uint4*)&As[ar * ASTR + ak + 4] = v;
            v.x = f2tf32(pb0.x); v.y = f2tf32(pb0.y); v.z = f2tf32(pb0.z); v.w = f2tf32(pb0.w);
            *(uint4*)&Bs[br * BSTR + bc] = v;
            v.x = f2tf32(pb1.x); v.y = f2tf32(pb1.y); v.z = f2tf32(pb1.z); v.w = f2tf32(pb1.w);
            *(uint4*)&Bs[br * BSTR + bc + 4] = v;
        }
        __syncthreads();

        if (k0 + BK < K) {
            pa0 = *(const float4*)(Ag + k0 + BK);
            pa1 = *(const float4*)(Ag + k0 + BK + 4);
            pb0 = *(const float4*)(Bg + (size_t)(k0 + BK) * N);
            pb1 = *(const float4*)(Bg + (size_t)(k0 + BK) * N + 4);
        }

        #pragma unroll
        for (int kk = 0; kk < 2; kk++) {
            const int ks = kk * 8;
            uint32_t af[4][4];
            #pragma unroll
            for (int mi = 0; mi < 4; mi++) {
                const int r0 = wm + mi * 16 + g;
                af[mi][0] = As[r0 * ASTR + ks + c];
                af[mi][1] = As[(r0 + 8) * ASTR + ks + c];
                af[mi][2] = As[r0 * ASTR + ks + c + 4];
                af[mi][3] = As[(r0 + 8) * ASTR + ks + c + 4];
            }
            uint32_t bf[4][2];
            #pragma unroll
            for (int ni = 0; ni < 4; ni++) {
                const int col = wn + ni * 8 + g;
                bf[ni][0] = Bs[(ks + c) * BSTR + col];
                bf[ni][1] = Bs[(ks + c + 4) * BSTR + col];
            }
            #pragma unroll
            for (int mi = 0; mi < 4; mi++)
                #pragma unroll
                for (int ni = 0; ni < 4; ni++)
                    mma_tf32(acc[mi][ni][0], acc[mi][ni][1], acc[mi][ni][2], acc[mi][ni][3],
                             af[mi][0], af[mi][1], af[mi][2], af[mi][3],
                             bf[ni][0], bf[ni][1]);
        }
        __syncthreads();
    }

    // epilogue
    #pragma unroll
    for (int mi = 0; mi < 4; mi++) {
        const int row = bm + wm + mi * 16 + g;
        #pragma unroll
        for (int ni = 0; ni < 4; ni++) {
            const int col = bn + wn + ni * 8 + 2 * c;
            *(float2*)&C[(size_t)row * N + col]       = make_float2(acc[mi][ni][0], acc[mi][ni][1]);
            *(float2*)&C[(size_t)(row + 8) * N + col] = make_float2(acc[mi][ni][2], acc[mi][ni][3]);
        }
    }
}

// ---------------- RoPE (interleaved pairs) ----------------
__global__ void rope_kernel(float* __restrict__ q,
                            const float* __restrict__ cosb,
                            const float* __restrict__ sinb,
                            int n_heads, int total)
{
    int idx = blockIdx.x * blockDim.x + threadIdx.x;
    if (idx >= total) return;
    int d2  = idx & 63;                       // HEAD_DIM/2 = 64
    int row = idx >> 6;                       // (b*S + s)*n_heads + h
    int s   = (row / n_heads) % SS;
    float c  = cosb[s * 64 + d2];
    float sn = sinb[s * 64 + d2];
    float* p = q + (size_t)row * HEAD_DIM + 2 * d2;
    float r = p[0], i = p[1];
    p[0] = r * c - i * sn;
    p[1] = r * sn + i * c;
}

// ---------------- causal GQA attention, online softmax ----------------
__global__ __launch_bounds__(1024) void attn_kernel(
    const float* __restrict__ Q, const float* __restrict__ K,
    const float* __restrict__ V, float* __restrict__ O)
{
    extern __shared__ float sm[];
    float* Ks = sm;                 // 64*128
    float* Vs = sm + 64 * 128;      // 64*128

    const int b    = blockIdx.z;
    const int h    = blockIdx.y;
    const int tile = blockIdx.x;
    const int kh   = h / (N_HEADS / N_KV_HEADS);
    const int warp = threadIdx.x >> 5;
    const int lane = threadIdx.x & 31;
    const int s    = tile * 32 + warp;
    const float scale = 0.08838834764831845f;   // 1/sqrt(128)

    const float4 qv = *(const float4*)&Q[((size_t)(b * SS + s) * N_HEADS + h) * HEAD_DIM + lane * 4];

    float m = -CUDART_INF_F, l = 0.f;
    float4 acc = make_float4(0.f, 0.f, 0.f, 0.f);

    const int smax   = tile * 32 + 31;
    const int ntiles = smax / 64 + 1;

    for (int jt = 0; jt < ntiles; jt++) {
        const int t0 = jt * 64;
        for (int i = threadIdx.x; i < 64 * 32; i += 1024) {
            int row = i >> 5, c4 = i & 31;
            size_t src = ((size_t)(b * SS + t0 + row) * N_KV_HEADS + kh) * HEAD_DIM + c4 * 4;
            *(float4*)&Ks[row * 128 + c4 * 4] = *(const float4*)&K[src];
            *(float4*)&Vs[row * 128 + c4 * 4] = *(const float4*)&V[src];
        }
        __syncthreads();

        const int jmax = min(63, s - t0);
        #pragma unroll 4
        for (int j = 0; j <= jmax; j++) {
            float4 kv = *(const float4*)&Ks[j * 128 + lane * 4];
            float x = qv.x * kv.x + qv.y * kv.y + qv.z * kv.z + qv.w * kv.w;
            #pragma unroll
            for (int o = 16; o; o >>= 1) x += __shfl_xor_sync(0xffffffffu, x, o);
            x *= scale;
            float mnew = fmaxf(m, x);
            float corr = __expf(m - mnew);
            float p    = __expf(x - mnew);
            l = l * corr + p;
            float4 vv = *(const float4*)&Vs[j * 128 + lane * 4];
            acc.x = acc.x * corr + p * vv.x;
            acc.y = acc.y * corr + p * vv.y;
            acc.z = acc.z * corr + p * vv.z;
            acc.w = acc.w * corr + p * vv.w;
            m = mnew;
        }
        __syncthreads();
    }

    const float inv = 1.f / l;
    float4 o4 = make_float4(acc.x * inv, acc.y * inv, acc.z * inv, acc.w * inv);
    *(float4*)&O[((size_t)(b * SS + s) * N_HEADS + h) * HEAD_DIM + lane * 4] = o4;
}

// ---------------- launch ----------------
extern "C" void kernel_launch(void* const* d_in, const int* in_sizes, int n_in,
                              void* d_out, int out_size)
{
    const float* x    = (const float*)d_in[0];
    const float* fcos = (const float*)d_in[1];
    const float* fsin = (const float*)d_in[2];
    const float* wq   = (const float*)d_in[3];
    const float* wk   = (const float*)d_in[4];
    const float* wv   = (const float*)d_in[5];
    const float* wo   = (const float*)d_in[6];
    float* out = (float*)d_out;

    float *Q, *K, *V, *O;
    cudaGetSymbolAddress((void**)&Q, g_Q);
    cudaGetSymbolAddress((void**)&K, g_K);
    cudaGetSymbolAddress((void**)&V, g_V);
    cudaGetSymbolAddress((void**)&O, g_O);

    // QKV projections (tf32 tensor cores)
    tf32_gemm<<<dim3(DIM / 128, ROWS / 128), 256>>>(x, wq, Q, ROWS, DIM, DIM);
    tf32_gemm<<<dim3(KV_DIM / 128, ROWS / 128), 256>>>(x, wk, K, ROWS, KV_DIM, DIM);
    tf32_gemm<<<dim3(KV_DIM / 128, ROWS / 128), 256>>>(x, wv, V, ROWS, KV_DIM, DIM);

    // RoPE on Q and K
    {
        int totQ = BB * SS * N_HEADS * (HEAD_DIM / 2);
        int totK = BB * SS * N_KV_HEADS * (HEAD_DIM / 2);
        rope_kernel<<<(totQ + 255) / 256, 256>>>(Q, fcos, fsin, N_HEADS, totQ);
        rope_kernel<<<(totK + 255) / 256, 256>>>(K, fcos, fsin, N_KV_HEADS, totK);
    }

    // attention
    {
        int smem = 2 * 64 * 128 * sizeof(float);   // 64 KB
        cudaFuncSetAttribute(attn_kernel, cudaFuncAttributeMaxDynamicSharedMemorySize, smem);
        attn_kernel<<<dim3(SS / 32, N_HEADS, BB), 1024, smem>>>(Q, K, V, O);
    }

    // output projection
    tf32_gemm<<<dim3(DIM / 128, ROWS / 128), 256>>>(O, wo, out, ROWS, DIM, DIM);
}

// round 3
// speedup vs baseline: 4.1784x; 3.1590x over previous
#include <cuda_runtime.h>
#include <cuda_bf16.h>
#include <math_constants.h>
#include <cstdint>

#define DIM 2048
#define N_HEADS 16
#define N_KV_HEADS 4
#define HEAD_DIM 128
#define BB 2
#define SS 2048
#define ROWS (BB*SS)              // 4096
#define KV_DIM (N_KV_HEADS*HEAD_DIM)  // 512

// ---------------- static scratch (no allocations allowed) ----------------
__device__ float g_Q[(size_t)ROWS * DIM];     // 32 MB
__device__ float g_K[(size_t)ROWS * KV_DIM];  // 8 MB
__device__ float g_V[(size_t)ROWS * KV_DIM];  // 8 MB
__device__ float g_O[(size_t)ROWS * DIM];     // 32 MB

// ---------------- tf32 helpers ----------------
__device__ __forceinline__ uint32_t f2tf32(float x) {
    uint32_t r;
    asm("cvt.rna.tf32.f32 %0, %1;" : "=r"(r) : "f"(x));
    return r;
}

__device__ __forceinline__ void mma_tf32(float& d0, float& d1, float& d2, float& d3,
                                         uint32_t a0, uint32_t a1, uint32_t a2, uint32_t a3,
                                         uint32_t b0, uint32_t b1) {
    asm volatile(
        "mma.sync.aligned.m16n8k8.row.col.f32.tf32.tf32.f32 "
        "{%0,%1,%2,%3}, {%4,%5,%6,%7}, {%8,%9}, {%0,%1,%2,%3};\n"
        : "+f"(d0), "+f"(d1), "+f"(d2), "+f"(d3)
        : "r"(a0), "r"(a1), "r"(a2), "r"(a3), "r"(b0), "r"(b1));
}

// ---------------- tf32 tensor-core GEMM ----------------
// C[M,N] = A[M,K] * B[K,N], row-major. Block 128x128x16, 256 thr, warp 64x32.
__global__ __launch_bounds__(256) void tf32_gemm(
    const float* __restrict__ A, const float* __restrict__ B,
    float* __restrict__ C, int M, int N, int K)
{
    constexpr int BM = 128, BN = 128, BK = 16;
    constexpr int ASTR = BK + 4;   // 20
    constexpr int BSTR = BN + 4;   // 132

    __shared__ uint32_t As[BM * ASTR];
    __shared__ uint32_t Bs[BK * BSTR];

    const int tid  = threadIdx.x;
    const int warp = tid >> 5;
    const int lane = tid & 31;
    const int g    = lane >> 2;
    const int c    = lane & 3;

    const int wm = (warp & 1) * 64;
    const int wn = (warp >> 1) * 32;

    const int bm = blockIdx.y * BM;
    const int bn = blockIdx.x * BN;

    const int ar = tid >> 1;
    const int ak = (tid & 1) * 8;
    const int br = tid >> 4;
    const int bc = (tid & 15) * 8;

    const float* Ag = A + (size_t)(bm + ar) * K + ak;
    const float* Bg = B + (size_t)br * N + bn + bc;

    float4 pa0, pa1, pb0, pb1;
    pa0 = *(const float4*)(Ag);
    pa1 = *(const float4*)(Ag + 4);
    pb0 = *(const float4*)(Bg);
    pb1 = *(const float4*)(Bg + 4);

    float acc[4][4][4];
    #pragma unroll
    for (int i = 0; i < 4; i++)
        #pragma unroll
        for (int j = 0; j < 4; j++)
            #pragma unroll
            for (int r = 0; r < 4; r++) acc[i][j][r] = 0.f;

    for (int k0 = 0; k0 < K; k0 += BK) {
        {
            uint4 v;
            v.x = f2tf32(pa0.x); v.y = f2tf32(pa0.y); v.z = f2tf32(pa0.z); v.w = f2tf32(pa0.w);
            *(uint4*)&As[ar * ASTR + ak] = v;
            v.x = f2tf32(pa1.x); v.y = f2tf32(pa1.y); v.z = f2tf32(pa1.z); v.w = f2tf32(pa1.w);
            *(uint4*)&As[ar * ASTR + ak + 4] = v;
            v.x = f2tf32(pb0.x); v.y = f2tf32(pb0.y); v.z = f2tf32(pb0.z); v.w = f2tf32(pb0.w);
            *(uint4*)&Bs[br * BSTR + bc] = v;
            v.x = f2tf32(pb1.x); v.y = f2tf32(pb1.y); v.z = f2tf32(pb1.z); v.w = f2tf32(pb1.w);
            *(uint4*)&Bs[br * BSTR + bc + 4] = v;
        }
        __syncthreads();

        if (k0 + BK < K) {
            pa0 = *(const float4*)(Ag + k0 + BK);
            pa1 = *(const float4*)(Ag + k0 + BK + 4);
            pb0 = *(const float4*)(Bg + (size_t)(k0 + BK) * N);
            pb1 = *(const float4*)(Bg + (size_t)(k0 + BK) * N + 4);
        }

        #pragma unroll
        for (int kk = 0; kk < 2; kk++) {
            const int ks = kk * 8;
            uint32_t af[4][4];
            #pragma unroll
            for (int mi = 0; mi < 4; mi++) {
                const int r0 = wm + mi * 16 + g;
                af[mi][0] = As[r0 * ASTR + ks + c];
                af[mi][1] = As[(r0 + 8) * ASTR + ks + c];
                af[mi][2] = As[r0 * ASTR + ks + c + 4];
                af[mi][3] = As[(r0 + 8) * ASTR + ks + c + 4];
            }
            uint32_t bf[4][2];
            #pragma unroll
            for (int ni = 0; ni < 4; ni++) {
                const int col = wn + ni * 8 + g;
                bf[ni][0] = Bs[(ks + c) * BSTR + col];
                bf[ni][1] = Bs[(ks + c + 4) * BSTR + col];
            }
            #pragma unroll
            for (int mi = 0; mi < 4; mi++)
                #pragma unroll
                for (int ni = 0; ni < 4; ni++)
                    mma_tf32(acc[mi][ni][0], acc[mi][ni][1], acc[mi][ni][2], acc[mi][ni][3],
                             af[mi][0], af[mi][1], af[mi][2], af[mi][3],
                             bf[ni][0], bf[ni][1]);
        }
        __syncthreads();
    }

    #pragma unroll
    for (int mi = 0; mi < 4; mi++) {
        const int row = bm + wm + mi * 16 + g;
        #pragma unroll
        for (int ni = 0; ni < 4; ni++) {
            const int col = bn + wn + ni * 8 + 2 * c;
            *(float2*)&C[(size_t)row * N + col]       = make_float2(acc[mi][ni][0], acc[mi][ni][1]);
            *(float2*)&C[(size_t)(row + 8) * N + col] = make_float2(acc[mi][ni][2], acc[mi][ni][3]);
        }
    }
}

// ---------------- FlashAttention (tf32 mma), RoPE fused into Q/K loads ----
// grid: (SS/128, N_HEADS, BB), block 256 (8 warps). Warp w owns q rows
// qt*128 + w*16 .. +15. K/V streamed in 64-key tiles.
// smem strides: Q/K 132 (bank=4g+c), V 136 (bank=8c+g), P 68 — all
// conflict-free for their fragment access patterns.
#define QSTR 132
#define KSTR 132
#define VSTR 136
#define PSTR 68
#define ATTN_SMEM ((128*QSTR + 64*KSTR + 64*VSTR + 128*PSTR) * 4)

__global__ __launch_bounds__(256) void flash_attn(
    const float* __restrict__ Qg, const float* __restrict__ Kg,
    const float* __restrict__ Vg, const float* __restrict__ cosb,
    const float* __restrict__ sinb, float* __restrict__ Og)
{
    extern __shared__ uint32_t sm[];
    uint32_t* Qs = sm;                    // [128][132]
    uint32_t* Ks = Qs + 128 * QSTR;       // [64][132]
    uint32_t* Vs = Ks + 64 * KSTR;        // [64][136]
    uint32_t* Ps = Vs + 64 * VSTR;        // [128][68]

    const int qt = blockIdx.x, h = blockIdx.y, b = blockIdx.z;
    const int kh = h >> 2;                // GQA: 16 heads -> 4 kv heads
    const int tid = threadIdx.x;
    const int warp = tid >> 5, lane = tid & 31;
    const int g = lane >> 2, c = lane & 3;
    const int wrow = warp * 16;
    const float scale = 0.08838834764831845f;   // 1/sqrt(128)

    // ---- load Q tile with RoPE, convert tf32 ----
    for (int i = tid; i < 128 * 32; i += 256) {
        int r = i >> 5, c4 = i & 31;
        int sq = qt * 128 + r;
        float4 v = *(const float4*)&Qg[((size_t)(b * SS + sq) * N_HEADS + h) * HEAD_DIM + c4 * 4];
        float2 cs = *(const float2*)&cosb[sq * 64 + c4 * 2];
        float2 sn = *(const float2*)&sinb[sq * 64 + c4 * 2];
        uint32_t* p = &Qs[r * QSTR + c4 * 4];
        p[0] = f2tf32(v.x * cs.x - v.y * sn.x);
        p[1] = f2tf32(v.x * sn.x + v.y * cs.x);
        p[2] = f2tf32(v.z * cs.y - v.w * sn.y);
        p[3] = f2tf32(v.z * sn.y + v.w * cs.y);
    }

    float o[16][4];
    #pragma unroll
    for (int nt = 0; nt < 16; nt++)
        #pragma unroll
        for (int r = 0; r < 4; r++) o[nt][r] = 0.f;

    float m0 = -CUDART_INF_F, m1 = -CUDART_INF_F, l0 = 0.f, l1 = 0.f;
    const int r0g = qt * 128 + wrow + g;   // this thread's first q row
    const int r1g = r0g + 8;

    const int nkt = (qt + 1) * 2;          // 64-key tiles to process

    for (int jt = 0; jt < nkt; jt++) {
        const int t0 = jt * 64;

        // ---- load K (RoPE) and V tiles, convert tf32 ----
        for (int i = tid; i < 64 * 32; i += 256) {
            int r = i >> 5, c4 = i & 31;
            int sk = t0 + r;
            size_t base = ((size_t)(b * SS + sk) * N_KV_HEADS + kh) * HEAD_DIM + c4 * 4;
            float4 kv = *(const float4*)&Kg[base];
            float2 cs = *(const float2*)&cosb[sk * 64 + c4 * 2];
            float2 sn = *(const float2*)&sinb[sk * 64 + c4 * 2];
            uint32_t* p = &Ks[r * KSTR + c4 * 4];
            p[0] = f2tf32(kv.x * cs.x - kv.y * sn.x);
            p[1] = f2tf32(kv.x * sn.x + kv.y * cs.x);
            p[2] = f2tf32(kv.z * cs.y - kv.w * sn.y);
            p[3] = f2tf32(kv.z * sn.y + kv.w * cs.y);
            float4 vv = *(const float4*)&Vg[base];
            uint4 u;
            u.x = f2tf32(vv.x); u.y = f2tf32(vv.y); u.z = f2tf32(vv.z); u.w = f2tf32(vv.w);
            *(uint4*)&Vs[r * VSTR + c4 * 4] = u;
        }
        __syncthreads();

        // ---- S = Q K^T (16 x 64 per warp) ----
        float s[8][4];
        #pragma unroll
        for (int ni = 0; ni < 8; ni++)
            #pragma unroll
            for (int r = 0; r < 4; r++) s[ni][r] = 0.f;

        #pragma unroll
        for (int ks = 0; ks < 16; ks++) {
            const int kb = ks * 8;
            uint32_t a0 = Qs[(wrow + g) * QSTR + kb + c];
            uint32_t a1 = Qs[(wrow + g + 8) * QSTR + kb + c];
            uint32_t a2 = Qs[(wrow + g) * QSTR + kb + c + 4];
            uint32_t a3 = Qs[(wrow + g + 8) * QSTR + kb + c + 4];
            #pragma unroll
            for (int ni = 0; ni < 8; ni++) {
                uint32_t b0 = Ks[(ni * 8 + g) * KSTR + kb + c];
                uint32_t b1 = Ks[(ni * 8 + g) * KSTR + kb + c + 4];
                mma_tf32(s[ni][0], s[ni][1], s[ni][2], s[ni][3], a0, a1, a2, a3, b0, b1);
            }
        }

        // ---- scale + causal mask ----
        #pragma unroll
        for (int ni = 0; ni < 8; ni++)
            #pragma unroll
            for (int r = 0; r < 4; r++) s[ni][r] *= scale;

        if (jt >= nkt - 2) {
            #pragma unroll
            for (int ni = 0; ni < 8; ni++) {
                int key0 = t0 + ni * 8 + 2 * c;
                if (key0 > r0g)     s[ni][0] = -CUDART_INF_F;
                if (key0 + 1 > r0g) s[ni][1] = -CUDART_INF_F;
                if (key0 > r1g)     s[ni][2] = -CUDART_INF_F;
                if (key0 + 1 > r1g) s[ni][3] = -CUDART_INF_F;
            }
        }

        // ---- online softmax ----
        float mx0 = -CUDART_INF_F, mx1 = -CUDART_INF_F;
        #pragma unroll
        for (int ni = 0; ni < 8; ni++) {
            mx0 = fmaxf(mx0, fmaxf(s[ni][0], s[ni][1]));
            mx1 = fmaxf(mx1, fmaxf(s[ni][2], s[ni][3]));
        }
        mx0 = fmaxf(mx0, __shfl_xor_sync(0xffffffffu, mx0, 1));
        mx0 = fmaxf(mx0, __shfl_xor_sync(0xffffffffu, mx0, 2));
        mx1 = fmaxf(mx1, __shfl_xor_sync(0xffffffffu, mx1, 1));
        mx1 = fmaxf(mx1, __shfl_xor_sync(0xffffffffu, mx1, 2));

        float mn0 = fmaxf(m0, mx0), mn1 = fmaxf(m1, mx1);
        float corr0 = __expf(m0 - mn0), corr1 = __expf(m1 - mn1);
        m0 = mn0; m1 = mn1;

        float ps0 = 0.f, ps1 = 0.f;
        #pragma unroll
        for (int ni = 0; ni < 8; ni++) {
            float p0 = __expf(s[ni][0] - mn0);
            float p1 = __expf(s[ni][1] - mn0);
            float p2 = __expf(s[ni][2] - mn1);
            float p3 = __expf(s[ni][3] - mn1);
            ps0 += p0 + p1;
            ps1 += p2 + p3;
            uint2 u;
            u.x = f2tf32(p0); u.y = f2tf32(p1);
            *(uint2*)&Ps[(wrow + g) * PSTR + ni * 8 + 2 * c] = u;
            u.x = f2tf32(p2); u.y = f2tf32(p3);
            *(uint2*)&Ps[(wrow + g + 8) * PSTR + ni * 8 + 2 * c] = u;
        }
        ps0 += __shfl_xor_sync(0xffffffffu, ps0, 1);
        ps0 += __shfl_xor_sync(0xffffffffu, ps0, 2);
        ps1 += __shfl_xor_sync(0xffffffffu, ps1, 1);
        ps1 += __shfl_xor_sync(0xffffffffu, ps1, 2);
        l0 = l0 * corr0 + ps0;
        l1 = l1 * corr1 + ps1;

        #pragma unroll
        for (int nt = 0; nt < 16; nt++) {
            o[nt][0] *= corr0; o[nt][1] *= corr0;
            o[nt][2] *= corr1; o[nt][3] *= corr1;
        }
        __syncwarp();

        // ---- O += P V ----
        #pragma unroll
        for (int ks = 0; ks < 8; ks++) {
            const int kb = ks * 8;
            uint32_t a0 = Ps[(wrow + g) * PSTR + kb + c];
            uint32_t a1 = Ps[(wrow + g + 8) * PSTR + kb + c];
            uint32_t a2 = Ps[(wrow + g) * PSTR + kb + c + 4];
            uint32_t a3 = Ps[(wrow + g + 8) * PSTR + kb + c + 4];
            #pragma unroll
            for (int nt = 0; nt < 16; nt++) {
                uint32_t b0 = Vs[(kb + c) * VSTR + nt * 8 + g];
                uint32_t b1 = Vs[(kb + c + 4) * VSTR + nt * 8 + g];
                mma_tf32(o[nt][0], o[nt][1], o[nt][2], o[nt][3], a0, a1, a2, a3, b0, b1);
            }
        }
        __syncthreads();
    }

    // ---- epilogue: normalize + store ----
    const float inv0 = 1.f / l0, inv1 = 1.f / l1;
    #pragma unroll
    for (int nt = 0; nt < 16; nt++) {
        int col = h * HEAD_DIM + nt * 8 + 2 * c;
        *(float2*)&Og[(size_t)(b * SS + r0g) * DIM + col] =
            make_float2(o[nt][0] * inv0, o[nt][1] * inv0);
        *(float2*)&Og[(size_t)(b * SS + r1g) * DIM + col] =
            make_float2(o[nt][2] * inv1, o[nt][3] * inv1);
    }
}

// ---------------- launch ----------------
extern "C" void kernel_launch(void* const* d_in, const int* in_sizes, int n_in,
                              void* d_out, int out_size)
{
    const float* x    = (const float*)d_in[0];
    const float* fcos = (const float*)d_in[1];
    const float* fsin = (const float*)d_in[2];
    const float* wq   = (const float*)d_in[3];
    const float* wk   = (const float*)d_in[4];
    const float* wv   = (const float*)d_in[5];
    const float* wo   = (const float*)d_in[6];
    float* out = (float*)d_out;

    float *Q, *K, *V, *O;
    cudaGetSymbolAddress((void**)&Q, g_Q);
    cudaGetSymbolAddress((void**)&K, g_K);
    cudaGetSymbolAddress((void**)&V, g_V);
    cudaGetSymbolAddress((void**)&O, g_O);

    // QKV projections (tf32 tensor cores)
    tf32_gemm<<<dim3(DIM / 128, ROWS / 128), 256>>>(x, wq, Q, ROWS, DIM, DIM);
    tf32_gemm<<<dim3(KV_DIM / 128, ROWS / 128), 256>>>(x, wk, K, ROWS, KV_DIM, DIM);
    tf32_gemm<<<dim3(KV_DIM / 128, ROWS / 128), 256>>>(x, wv, V, ROWS, KV_DIM, DIM);

    // FlashAttention with fused RoPE
    {
        cudaFuncSetAttribute(flash_attn, cudaFuncAttributeMaxDynamicSharedMemorySize, ATTN_SMEM);
        flash_attn<<<dim3(SS / 128, N_HEADS, BB), 256, ATTN_SMEM>>>(Q, K, V, fcos, fsin, O);
    }

    // output projection
    tf32_gemm<<<dim3(DIM / 128, ROWS / 128), 256>>>(O, wo, out, ROWS, DIM, DIM);
}

// round 4
// speedup vs baseline: 4.7984x; 1.1484x over previous
#include <cuda_runtime.h>
#include <cuda_bf16.h>
#include <math_constants.h>
#include <cstdint>

#define DIM 2048
#define N_HEADS 16
#define N_KV_HEADS 4
#define HEAD_DIM 128
#define BB 2
#define SS 2048
#define ROWS (BB*SS)                  // 4096
#define KV_DIM (N_KV_HEADS*HEAD_DIM)  // 512

// ---------------- static scratch (no allocations allowed) ----------------
__device__ float g_Q[(size_t)ROWS * DIM];
__device__ float g_K[(size_t)ROWS * KV_DIM];
__device__ float g_V[(size_t)ROWS * KV_DIM];
__device__ float g_O[(size_t)ROWS * DIM];

// ---------------- helpers ----------------
__device__ __forceinline__ uint32_t f2tf32(float x) {
    uint32_t r;
    asm("cvt.rna.tf32.f32 %0, %1;" : "=r"(r) : "f"(x));
    return r;
}
__device__ __forceinline__ float tf32r(float x) { return __uint_as_float(f2tf32(x)); }

__device__ __forceinline__ void mma_tf32(float& d0, float& d1, float& d2, float& d3,
                                         uint32_t a0, uint32_t a1, uint32_t a2, uint32_t a3,
                                         uint32_t b0, uint32_t b1) {
    asm volatile(
        "mma.sync.aligned.m16n8k8.row.col.f32.tf32.tf32.f32 "
        "{%0,%1,%2,%3}, {%4,%5,%6,%7}, {%8,%9}, {%0,%1,%2,%3};\n"
        : "+f"(d0), "+f"(d1), "+f"(d2), "+f"(d3)
        : "r"(a0), "r"(a1), "r"(a2), "r"(a3), "r"(b0), "r"(b1));
}

__device__ __forceinline__ void cp16(uint32_t dst, const void* src) {
    asm volatile("cp.async.cg.shared.global [%0], [%1], 16;\n" :: "r"(dst), "l"(src));
}
__device__ __forceinline__ uint32_t sptr(const void* p) {
    return (uint32_t)__cvta_generic_to_shared(p);
}
#define CP_COMMIT asm volatile("cp.async.commit_group;\n" ::: "memory")
#define CP_WAIT(N) asm volatile("cp.async.wait_group %0;\n" :: "n"(N) : "memory")

// ---------------- tf32 tensor-core GEMM, double-buffered ----------------
// C[M,N] = A[M,K] * B[K,N] row-major. Block 128 x BN x 16, 256 threads,
// warps 2 x (BN/WN), warp tile 64 x WN. One __syncthreads per K-iter.
template<int BN, int WN, bool TF32OUT>
__global__ __launch_bounds__(256, 1) void tf32_gemm(
    const float* __restrict__ A, const float* __restrict__ B,
    float* __restrict__ C, int M, int N, int K)
{
    constexpr int BM = 128, BK = 16;
    constexpr int ASTR = BK + 4;     // banks 4g+c : conflict-free frag LDS
    constexpr int BSTR = BN + 8;     // banks 8c+g : conflict-free frag LDS
    constexpr int NB4  = BN / 64;    // float4 B loads per thread
    constexpr int NNI  = WN / 8;
    constexpr int ASZ = BM * ASTR, BSZ = BK * BSTR;

    extern __shared__ uint32_t smu[];
    uint32_t* As = smu;              // [2][ASZ]
    uint32_t* Bs = smu + 2 * ASZ;    // [2][BSZ]

    const int tid = threadIdx.x, warp = tid >> 5, lane = tid & 31;
    const int g = lane >> 2, c = lane & 3;
    const int wm = (warp & 1) * 64, wn = (warp >> 1) * WN;
    const int bm = blockIdx.y * BM, bn = blockIdx.x * BN;

    const int ar = tid >> 1, ak = (tid & 1) * 8;
    const int br = tid >> 4, bc = (tid & 15) * (BN / 16);

    const float* Ag = A + (size_t)(bm + ar) * K + ak;
    const float* Bg = B + (size_t)br * N + bn + bc;

    float4 pa0, pa1, pb[NB4];
    pa0 = *(const float4*)Ag;
    pa1 = *(const float4*)(Ag + 4);
    #pragma unroll
    for (int j = 0; j < NB4; j++) pb[j] = *(const float4*)(Bg + j * 4);

    auto stash = [&](int buf) {
        uint32_t* as = As + buf * ASZ;
        uint32_t* bs = Bs + buf * BSZ;
        uint4 v;
        v.x = f2tf32(pa0.x); v.y = f2tf32(pa0.y); v.z = f2tf32(pa0.z); v.w = f2tf32(pa0.w);
        *(uint4*)&as[ar * ASTR + ak] = v;
        v.x = f2tf32(pa1.x); v.y = f2tf32(pa1.y); v.z = f2tf32(pa1.z); v.w = f2tf32(pa1.w);
        *(uint4*)&as[ar * ASTR + ak + 4] = v;
        #pragma unroll
        for (int j = 0; j < NB4; j++) {
            v.x = f2tf32(pb[j].x); v.y = f2tf32(pb[j].y);
            v.z = f2tf32(pb[j].z); v.w = f2tf32(pb[j].w);
            *(uint4*)&bs[br * BSTR + bc + j * 4] = v;
        }
    };

    stash(0);

    float acc[4][NNI][4];
    #pragma unroll
    for (int mi = 0; mi < 4; mi++)
        #pragma unroll
        for (int ni = 0; ni < NNI; ni++)
            #pragma unroll
            for (int r = 0; r < 4; r++) acc[mi][ni][r] = 0.f;

    __syncthreads();

    int cur = 0;
    for (int k0 = 0; k0 < K; k0 += BK) {
        const bool nxt = (k0 + BK) < K;
        if (nxt) {
            pa0 = *(const float4*)(Ag + k0 + BK);
            pa1 = *(const float4*)(Ag + k0 + BK + 4);
            #pragma unroll
            for (int j = 0; j < NB4; j++)
                pb[j] = *(const float4*)(Bg + (size_t)(k0 + BK) * N + j * 4);
        }

        const uint32_t* as = As + cur * ASZ;
        const uint32_t* bs = Bs + cur * BSZ;
        #pragma unroll
        for (int kk = 0; kk < 2; kk++) {
            const int kb = kk * 8;
            uint32_t af[4][4];
            #pragma unroll
            for (int mi = 0; mi < 4; mi++) {
                const int r0 = wm + mi * 16 + g;
                af[mi][0] = as[r0 * ASTR + kb + c];
                af[mi][1] = as[(r0 + 8) * ASTR + kb + c];
                af[mi][2] = as[r0 * ASTR + kb + c + 4];
                af[mi][3] = as[(r0 + 8) * ASTR + kb + c + 4];
            }
            uint32_t bf[NNI][2];
            #pragma unroll
            for (int ni = 0; ni < NNI; ni++) {
                const int col = wn + ni * 8 + g;
                bf[ni][0] = bs[(kb + c) * BSTR + col];
                bf[ni][1] = bs[(kb + c + 4) * BSTR + col];
            }
            #pragma unroll
            for (int mi = 0; mi < 4; mi++)
                #pragma unroll
                for (int ni = 0; ni < NNI; ni++)
                    mma_tf32(acc[mi][ni][0], acc[mi][ni][1], acc[mi][ni][2], acc[mi][ni][3],
                             af[mi][0], af[mi][1], af[mi][2], af[mi][3],
                             bf[ni][0], bf[ni][1]);
        }

        if (nxt) stash(cur ^ 1);
        __syncthreads();
        cur ^= 1;
    }

    #pragma unroll
    for (int mi = 0; mi < 4; mi++) {
        const int row = bm + wm + mi * 16 + g;
        #pragma unroll
        for (int ni = 0; ni < NNI; ni++) {
            const int col = bn + wn + ni * 8 + 2 * c;
            float v0 = acc[mi][ni][0], v1 = acc[mi][ni][1];
            float v2 = acc[mi][ni][2], v3 = acc[mi][ni][3];
            if (TF32OUT) { v0 = tf32r(v0); v1 = tf32r(v1); v2 = tf32r(v2); v3 = tf32r(v3); }
            *(float2*)&C[(size_t)row * N + col]       = make_float2(v0, v1);
            *(float2*)&C[(size_t)(row + 8) * N + col] = make_float2(v2, v3);
        }
    }
}

// ---------------- RoPE + tf32 rounding (in place) ----------------
__global__ void rope_kernel(float* __restrict__ q,
                            const float* __restrict__ cosb,
                            const float* __restrict__ sinb,
                            int n_heads, int total)
{
    int idx = blockIdx.x * blockDim.x + threadIdx.x;
    if (idx >= total) return;
    int d2  = idx & 63;                 // HEAD_DIM/2 = 64
    int row = idx >> 6;
    int s   = (row / n_heads) % SS;
    float c  = cosb[s * 64 + d2];
    float sn = sinb[s * 64 + d2];
    float* p = q + (size_t)row * HEAD_DIM + 2 * d2;
    float r = p[0], i = p[1];
    p[0] = tf32r(r * c - i * sn);
    p[1] = tf32r(r * sn + i * c);
}

// ---------------- FlashAttention, cp.async double-buffered K/V ----------
// Q/K/V in gmem already hold tf32-valued floats (rope/GEMM pre-rounded).
// grid (SS/128, N_HEADS, BB), 256 thr (8 warps x 16 q rows). 32-key stages.
#define KT   32
#define QSTR 132
#define KSTR 132
#define VSTR 136
#define PSTR 68
#define ATTN_SMEM ((128*QSTR + 2*KT*KSTR + 2*KT*VSTR + 128*PSTR) * 4)

__global__ __launch_bounds__(256) void flash_attn(
    const float* __restrict__ Qg, const float* __restrict__ Kg,
    const float* __restrict__ Vg, float* __restrict__ Og)
{
    extern __shared__ uint32_t sm[];
    uint32_t* Qs = sm;                        // [128][QSTR]
    uint32_t* Ks = Qs + 128 * QSTR;           // [2][KT][KSTR]
    uint32_t* Vs = Ks + 2 * KT * KSTR;        // [2][KT][VSTR]
    uint32_t* Ps = Vs + 2 * KT * VSTR;        // [128][PSTR]

    const int qt = blockIdx.x, h = blockIdx.y, b = blockIdx.z;
    const int kh = h >> 2;
    const int tid = threadIdx.x;
    const int warp = tid >> 5, lane = tid & 31;
    const int g = lane >> 2, c = lane & 3;
    const int wrow = warp * 16;
    const float scale = 0.08838834764831845f;  // 1/sqrt(128)

    const int nkt = (qt + 1) * 4;              // 32-key tiles

    // ---- issue Q tile (group 0, together with stage 0) ----
    for (int i = tid; i < 128 * 32; i += 256) {
        int r = i >> 5, c4 = i & 31;
        cp16(sptr(&Qs[r * QSTR + c4 * 4]),
             &Qg[((size_t)(b * SS + qt * 128 + r) * N_HEADS + h) * HEAD_DIM + c4 * 4]);
    }
    // ---- issue K/V stage s into buffer s&1 ----
    auto kv_issue = [&](int s) {
        const int buf = s & 1, t0 = s * KT;
        for (int i = tid; i < KT * 32; i += 256) {
            int r = i >> 5, c4 = i & 31;
            size_t base = ((size_t)(b * SS + t0 + r) * N_KV_HEADS + kh) * HEAD_DIM + c4 * 4;
            cp16(sptr(&Ks[buf * KT * KSTR + r * KSTR + c4 * 4]), &Kg[base]);
            cp16(sptr(&Vs[buf * KT * VSTR + r * VSTR + c4 * 4]), &Vg[base]);
        }
    };
    kv_issue(0);
    CP_COMMIT;            // group: Q + stage0
    kv_issue(1);
    CP_COMMIT;            // group: stage1

    float o[16][4];
    #pragma unroll
    for (int nt = 0; nt < 16; nt++)
        #pragma unroll
        for (int r = 0; r < 4; r++) o[nt][r] = 0.f;

    float m0 = -CUDART_INF_F, m1 = -CUDART_INF_F, l0 = 0.f, l1 = 0.f;
    const int r0g = qt * 128 + wrow + g;
    const int r1g = r0g + 8;

    for (int jt = 0; jt < nkt; jt++) {
        if (jt + 1 < nkt) { CP_WAIT(1); } else { CP_WAIT(0); }
        __syncthreads();

        const int buf = jt & 1, t0 = jt * KT;
        const uint32_t* Kb = Ks + buf * KT * KSTR;
        const uint32_t* Vb = Vs + buf * KT * VSTR;

        // ---- S = Q K^T (16 x 32 per warp) ----
        float s[4][4];
        #pragma unroll
        for (int ni = 0; ni < 4; ni++)
            #pragma unroll
            for (int r = 0; r < 4; r++) s[ni][r] = 0.f;

        #pragma unroll
        for (int ks = 0; ks < 16; ks++) {
            const int kb = ks * 8;
            uint32_t a0 = Qs[(wrow + g) * QSTR + kb + c];
            uint32_t a1 = Qs[(wrow + g + 8) * QSTR + kb + c];
            uint32_t a2 = Qs[(wrow + g) * QSTR + kb + c + 4];
            uint32_t a3 = Qs[(wrow + g + 8) * QSTR + kb + c + 4];
            #pragma unroll
            for (int ni = 0; ni < 4; ni++) {
                uint32_t b0 = Kb[(ni * 8 + g) * KSTR + kb + c];
                uint32_t b1 = Kb[(ni * 8 + g) * KSTR + kb + c + 4];
                mma_tf32(s[ni][0], s[ni][1], s[ni][2], s[ni][3], a0, a1, a2, a3, b0, b1);
            }
        }

        #pragma unroll
        for (int ni = 0; ni < 4; ni++)
            #pragma unroll
            for (int r = 0; r < 4; r++) s[ni][r] *= scale;

        if (jt >= nkt - 4) {   // diagonal block
            #pragma unroll
            for (int ni = 0; ni < 4; ni++) {
                int key0 = t0 + ni * 8 + 2 * c;
                if (key0 > r0g)     s[ni][0] = -CUDART_INF_F;
                if (key0 + 1 > r0g) s[ni][1] = -CUDART_INF_F;
                if (key0 > r1g)     s[ni][2] = -CUDART_INF_F;
                if (key0 + 1 > r1g) s[ni][3] = -CUDART_INF_F;
            }
        }

        // ---- online softmax ----
        float mx0 = -CUDART_INF_F, mx1 = -CUDART_INF_F;
        #pragma unroll
        for (int ni = 0; ni < 4; ni++) {
            mx0 = fmaxf(mx0, fmaxf(s[ni][0], s[ni][1]));
            mx1 = fmaxf(mx1, fmaxf(s[ni][2], s[ni][3]));
        }
        mx0 = fmaxf(mx0, __shfl_xor_sync(0xffffffffu, mx0, 1));
        mx0 = fmaxf(mx0, __shfl_xor_sync(0xffffffffu, mx0, 2));
        mx1 = fmaxf(mx1, __shfl_xor_sync(0xffffffffu, mx1, 1));
        mx1 = fmaxf(mx1, __shfl_xor_sync(0xffffffffu, mx1, 2));

        float mn0 = fmaxf(m0, mx0), mn1 = fmaxf(m1, mx1);
        float corr0 = __expf(m0 - mn0), corr1 = __expf(m1 - mn1);
        m0 = mn0; m1 = mn1;

        float ps0 = 0.f, ps1 = 0.f;
        #pragma unroll
        for (int ni = 0; ni < 4; ni++) {
            float p0 = __expf(s[ni][0] - mn0);
            float p1 = __expf(s[ni][1] - mn0);
            float p2 = __expf(s[ni][2] - mn1);
            float p3 = __expf(s[ni][3] - mn1);
            ps0 += p0 + p1;
            ps1 += p2 + p3;
            uint2 u;
            u.x = f2tf32(p0); u.y = f2tf32(p1);
            *(uint2*)&Ps[(wrow + g) * PSTR + ni * 8 + 2 * c] = u;
            u.x = f2tf32(p2); u.y = f2tf32(p3);
            *(uint2*)&Ps[(wrow + g + 8) * PSTR + ni * 8 + 2 * c] = u;
        }
        ps0 += __shfl_xor_sync(0xffffffffu, ps0, 1);
        ps0 += __shfl_xor_sync(0xffffffffu, ps0, 2);
        ps1 += __shfl_xor_sync(0xffffffffu, ps1, 1);
        ps1 += __shfl_xor_sync(0xffffffffu, ps1, 2);
        l0 = l0 * corr0 + ps0;
        l1 = l1 * corr1 + ps1;

        #pragma unroll
        for (int nt = 0; nt < 16; nt++) {
            o[nt][0] *= corr0; o[nt][1] *= corr0;
            o[nt][2] *= corr1; o[nt][3] *= corr1;
        }
        __syncwarp();

        // ---- O += P V ----
        #pragma unroll
        for (int ks = 0; ks < 4; ks++) {
            const int kb = ks * 8;
            uint32_t a0 = Ps[(wrow + g) * PSTR + kb + c];
            uint32_t a1 = Ps[(wrow + g + 8) * PSTR + kb + c];
            uint32_t a2 = Ps[(wrow + g) * PSTR + kb + c + 4];
            uint32_t a3 = Ps[(wrow + g + 8) * PSTR + kb + c + 4];
            #pragma unroll
            for (int nt = 0; nt < 16; nt++) {
                uint32_t b0 = Vb[(kb + c) * VSTR + nt * 8 + g];
                uint32_t b1 = Vb[(kb + c + 4) * VSTR + nt * 8 + g];
                mma_tf32(o[nt][0], o[nt][1], o[nt][2], o[nt][3], a0, a1, a2, a3, b0, b1);
            }
        }
        __syncthreads();

        if (jt + 2 < nkt) { kv_issue(jt + 2); CP_COMMIT; }
    }

    // ---- epilogue: normalize + store ----
    const float inv0 = 1.f / l0, inv1 = 1.f / l1;
    #pragma unroll
    for (int nt = 0; nt < 16; nt++) {
        int col = h * HEAD_DIM + nt * 8 + 2 * c;
        *(float2*)&Og[(size_t)(b * SS + r0g) * DIM + col] =
            make_float2(o[nt][0] * inv0, o[nt][1] * inv0);
        *(float2*)&Og[(size_t)(b * SS + r1g) * DIM + col] =
            make_float2(o[nt][2] * inv1, o[nt][3] * inv1);
    }
}

// ---------------- launch ----------------
extern "C" void kernel_launch(void* const* d_in, const int* in_sizes, int n_in,
                              void* d_out, int out_size)
{
    const float* x    = (const float*)d_in[0];
    const float* fcos = (const float*)d_in[1];
    const float* fsin = (const float*)d_in[2];
    const float* wq   = (const float*)d_in[3];
    const float* wk   = (const float*)d_in[4];
    const float* wv   = (const float*)d_in[5];
    const float* wo   = (const float*)d_in[6];
    float* out = (float*)d_out;

    float *Q, *K, *V, *O;
    cudaGetSymbolAddress((void**)&Q, g_Q);
    cudaGetSymbolAddress((void**)&K, g_K);
    cudaGetSymbolAddress((void**)&V, g_V);
    cudaGetSymbolAddress((void**)&O, g_O);

    // smem sizes for the GEMM variants
    const int smem_big = 2 * (128 * 20 + 16 * (256 + 8)) * 4;   // 54,272 B
    const int smem_kv  = 2 * (128 * 20 + 16 * (128 + 8)) * 4;   // 37,888 B

    cudaFuncSetAttribute((const void*)tf32_gemm<256, 64, false>,
                         cudaFuncAttributeMaxDynamicSharedMemorySize, smem_big);
    cudaFuncSetAttribute((const void*)tf32_gemm<128, 32, false>,
                         cudaFuncAttributeMaxDynamicSharedMemorySize, smem_kv);
    cudaFuncSetAttribute((const void*)tf32_gemm<128, 32, true>,
                         cudaFuncAttributeMaxDynamicSharedMemorySize, smem_kv);
    cudaFuncSetAttribute((const void*)flash_attn,
                         cudaFuncAttributeMaxDynamicSharedMemorySize, ATTN_SMEM);

    // QKV projections
    tf32_gemm<256, 64, false><<<dim3(DIM / 256, ROWS / 128), 256, smem_big>>>(x, wq, Q, ROWS, DIM, DIM);
    tf32_gemm<128, 32, false><<<dim3(KV_DIM / 128, ROWS / 128), 256, smem_kv>>>(x, wk, K, ROWS, KV_DIM, DIM);
    tf32_gemm<128, 32, true ><<<dim3(KV_DIM / 128, ROWS / 128), 256, smem_kv>>>(x, wv, V, ROWS, KV_DIM, DIM);

    // RoPE (+ tf32 rounding) on Q and K
    {
        int totQ = BB * SS * N_HEADS * (HEAD_DIM / 2);
        int totK = BB * SS * N_KV_HEADS * (HEAD_DIM / 2);
        rope_kernel<<<(totQ + 255) / 256, 256>>>(Q, fcos, fsin, N_HEADS, totQ);
        rope_kernel<<<(totK + 255) / 256, 256>>>(K, fcos, fsin, N_KV_HEADS, totK);
    }

    // FlashAttention
    flash_attn<<<dim3(SS / 128, N_HEADS, BB), 256, ATTN_SMEM>>>(Q, K, V, O);

    // output projection
    tf32_gemm<256, 64, false><<<dim3(DIM / 256, ROWS / 128), 256, smem_big>>>(O, wo, out, ROWS, DIM, DIM);
}

// round 5
// speedup vs baseline: 10.2782x; 2.1420x over previous
#include <cuda_runtime.h>
#include <cuda_fp16.h>
#include <math_constants.h>
#include <cstdint>

#define DIM 2048
#define N_HEADS 16
#define N_KV_HEADS 4
#define HEAD_DIM 128
#define BB 2
#define SS 2048
#define ROWS (BB*SS)                  // 4096
#define KV_DIM (N_KV_HEADS*HEAD_DIM)  // 512

// ---------------- static scratch (no allocations allowed) ----------------
__device__ __half g_xh [(size_t)ROWS * DIM];
__device__ __half g_wqh[(size_t)DIM * DIM];
__device__ __half g_wkh[(size_t)DIM * KV_DIM];
__device__ __half g_wvh[(size_t)DIM * KV_DIM];
__device__ __half g_woh[(size_t)DIM * DIM];
__device__ float  g_Qf [(size_t)ROWS * DIM];
__device__ float  g_Kf [(size_t)ROWS * KV_DIM];
__device__ __half g_Qh [(size_t)ROWS * DIM];
__device__ __half g_Kh [(size_t)ROWS * KV_DIM];
__device__ __half g_Vh [(size_t)ROWS * KV_DIM];
__device__ __half g_Oh [(size_t)ROWS * DIM];

// ---------------- low-level helpers ----------------
__device__ __forceinline__ uint32_t sptr(const void* p) {
    return (uint32_t)__cvta_generic_to_shared(p);
}
__device__ __forceinline__ void cp16(uint32_t dst, const void* src) {
    asm volatile("cp.async.cg.shared.global [%0], [%1], 16;\n" :: "r"(dst), "l"(src));
}
#define CP_COMMIT asm volatile("cp.async.commit_group;\n" ::: "memory")
#define CP_WAIT(N) asm volatile("cp.async.wait_group %0;\n" :: "n"(N) : "memory")

__device__ __forceinline__ void ldsm_x4(uint32_t* r, uint32_t a) {
    asm volatile("ldmatrix.sync.aligned.m8n8.x4.shared.b16 {%0,%1,%2,%3}, [%4];"
                 : "=r"(r[0]), "=r"(r[1]), "=r"(r[2]), "=r"(r[3]) : "r"(a));
}
__device__ __forceinline__ void ldsm_x4t(uint32_t* r, uint32_t a) {
    asm volatile("ldmatrix.sync.aligned.m8n8.x4.trans.shared.b16 {%0,%1,%2,%3}, [%4];"
                 : "=r"(r[0]), "=r"(r[1]), "=r"(r[2]), "=r"(r[3]) : "r"(a));
}
__device__ __forceinline__ void mma_f16(float* d, const uint32_t* a, uint32_t b0, uint32_t b1) {
    asm volatile(
        "mma.sync.aligned.m16n8k16.row.col.f32.f16.f16.f32 "
        "{%0,%1,%2,%3}, {%4,%5,%6,%7}, {%8,%9}, {%0,%1,%2,%3};"
        : "+f"(d[0]), "+f"(d[1]), "+f"(d[2]), "+f"(d[3])
        : "r"(a[0]), "r"(a[1]), "r"(a[2]), "r"(a[3]), "r"(b0), "r"(b1));
}

// ---------------- fp32 -> fp16 convert ----------------
__global__ void f2h(const float* __restrict__ in, __half* __restrict__ out, int n2) {
    int i = blockIdx.x * blockDim.x + threadIdx.x;
    if (i < n2) {
        float2 v = ((const float2*)in)[i];
        ((__half2*)out)[i] = __floats2half2_rn(v.x, v.y);
    }
}

// ---------------- RoPE fp32 -> fp16 ----------------
__global__ void rope_h(const float* __restrict__ in, __half* __restrict__ out,
                       const float* __restrict__ cosb, const float* __restrict__ sinb,
                       int n_heads, int total)
{
    int idx = blockIdx.x * blockDim.x + threadIdx.x;
    if (idx >= total) return;
    int d2  = idx & 63;                 // HEAD_DIM/2
    int row = idx >> 6;
    int s   = (row / n_heads) % SS;
    float c  = cosb[s * 64 + d2];
    float sn = sinb[s * 64 + d2];
    const float* p = in + (size_t)row * HEAD_DIM + 2 * d2;
    float r = p[0], i2 = p[1];
    ((__half2*)out)[(size_t)row * 64 + d2] =
        __floats2half2_rn(r * c - i2 * sn, r * sn + i2 * c);
}

// ---------------- fp16 tensor-core GEMM, 4-stage cp.async --------------
// C[M,N] = A[M,K] * B[K,N], A/B fp16 row-major, C fp32 or fp16.
// Block 128 x BN x 32, 256 threads, warps 2 x (BN/WN), warp tile 64 x WN.
template<int BN, int WN, bool HOUT>
__global__ __launch_bounds__(256, 1) void hgemm(
    const __half* __restrict__ A, const __half* __restrict__ B,
    void* __restrict__ C, int M, int N, int K)
{
    constexpr int BM = 128, BK = 32, STG = 4;
    constexpr int ASTR = BK + 8;           // halves; 20-word rows: LDSM conflict-free
    constexpr int BSTR = BN + 8;           // halves; 4-bank row shift: conflict-free
    constexpr int ASZB = BM * ASTR * 2;    // stage bytes
    constexpr int BSZB = BK * BSTR * 2;
    constexpr int NNI  = WN / 8;
    constexpr int CPB  = BN / 8;           // B 16B-chunks per row

    extern __shared__ char smem[];
    const uint32_t sA = sptr(smem);
    const uint32_t sB = sA + STG * ASZB;

    const int tid = threadIdx.x, warp = tid >> 5, lane = tid & 31;
    const int g = lane >> 2, c = lane & 3;
    const int wm = (warp & 1) * 64, wn = (warp >> 1) * WN;
    const int bm = blockIdx.y * BM, bn = blockIdx.x * BN;

    auto issue = [&](int kt) {
        const int st = kt & (STG - 1);
        const uint32_t da = sA + st * ASZB;
        const __half* ga = A + (size_t)bm * K + (size_t)kt * BK;
        #pragma unroll
        for (int i = tid; i < 128 * 4; i += 256) {
            int r = i >> 2, ch = i & 3;
            cp16(da + (r * ASTR + ch * 8) * 2, ga + (size_t)r * K + ch * 8);
        }
        const uint32_t db = sB + st * BSZB;
        const __half* gb = B + (size_t)kt * BK * N + bn;
        #pragma unroll
        for (int i = tid; i < 32 * CPB; i += 256) {
            int r = i / CPB, ch = i % CPB;
            cp16(db + (r * BSTR + ch * 8) * 2, gb + (size_t)r * N + ch * 8);
        }
    };

    issue(0); CP_COMMIT;
    issue(1); CP_COMMIT;
    issue(2); CP_COMMIT;

    float acc[4][NNI][4];
    #pragma unroll
    for (int mi = 0; mi < 4; mi++)
        #pragma unroll
        for (int ni = 0; ni < NNI; ni++)
            #pragma unroll
            for (int r = 0; r < 4; r++) acc[mi][ni][r] = 0.f;

    // per-lane ldmatrix base addresses
    const uint32_t aBase = sA + (((wm + (lane & 15)) * ASTR) + ((lane >> 4) << 3)) * 2;
    const uint32_t bBase = sB + (((((lane >> 3) & 1) * 8 + (lane & 7)) * BSTR)
                                 + wn + ((lane >> 4) << 3)) * 2;

    const int NT = K / BK;
    for (int kt = 0; kt < NT; kt++) {
        CP_WAIT(2);
        __syncthreads();
        if (kt + 3 < NT) issue(kt + 3);
        CP_COMMIT;

        const int st = kt & (STG - 1);
        const uint32_t ab = aBase + st * ASZB;
        const uint32_t bb = bBase + st * BSZB;

        #pragma unroll
        for (int kk = 0; kk < 2; kk++) {
            const int kb = kk * 16;
            uint32_t af[4][4];
            #pragma unroll
            for (int mi = 0; mi < 4; mi++)
                ldsm_x4(af[mi], ab + (mi * 16 * ASTR + kb) * 2);
            uint32_t bf[NNI][2];
            #pragma unroll
            for (int nip = 0; nip < NNI / 2; nip++) {
                uint32_t t[4];
                ldsm_x4t(t, bb + (kb * BSTR + nip * 16) * 2);
                bf[2 * nip][0] = t[0]; bf[2 * nip][1] = t[1];
                bf[2 * nip + 1][0] = t[2]; bf[2 * nip + 1][1] = t[3];
            }
            #pragma unroll
            for (int mi = 0; mi < 4; mi++)
                #pragma unroll
                for (int ni = 0; ni < NNI; ni++)
                    mma_f16(acc[mi][ni], af[mi], bf[ni][0], bf[ni][1]);
        }
    }

    // epilogue
    #pragma unroll
    for (int mi = 0; mi < 4; mi++) {
        const int row = bm + wm + mi * 16 + g;
        #pragma unroll
        for (int ni = 0; ni < NNI; ni++) {
            const int col = bn + wn + ni * 8 + 2 * c;
            if (HOUT) {
                __half* Ch = (__half*)C;
                *(__half2*)&Ch[(size_t)row * N + col] =
                    __floats2half2_rn(acc[mi][ni][0], acc[mi][ni][1]);
                *(__half2*)&Ch[(size_t)(row + 8) * N + col] =
                    __floats2half2_rn(acc[mi][ni][2], acc[mi][ni][3]);
            } else {
                float* Cf = (float*)C;
                *(float2*)&Cf[(size_t)row * N + col] =
                    make_float2(acc[mi][ni][0], acc[mi][ni][1]);
                *(float2*)&Cf[(size_t)(row + 8) * N + col] =
                    make_float2(acc[mi][ni][2], acc[mi][ni][3]);
            }
        }
    }
}

// ---------------- FlashAttention fp16, 3-stage cp.async K/V -------------
#define KT   32
#define QSTR 136
#define KSTR 136
#define VSTR 136
#define PSTR 40
#define KSTGB (KT*KSTR*2)
#define VSTGB (KT*VSTR*2)
#define ATTN_SMEM ((128*QSTR + 3*KT*KSTR + 3*KT*VSTR + 128*PSTR) * 2)

__global__ __launch_bounds__(256, 2) void flash_attn(
    const __half* __restrict__ Qg, const __half* __restrict__ Kg,
    const __half* __restrict__ Vg, __half* __restrict__ Og)
{
    extern __shared__ char smem[];
    __half* shQ = (__half*)smem;              // [128][QSTR]
    __half* shK = shQ + 128 * QSTR;           // [3][KT][KSTR]
    __half* shV = shK + 3 * KT * KSTR;        // [3][KT][VSTR]
    __half* shP = shV + 3 * KT * VSTR;        // [128][PSTR]
    const uint32_t sQ = sptr(shQ), sK = sptr(shK), sV = sptr(shV), sP = sptr(shP);

    const int qt = blockIdx.x, h = blockIdx.y, b = blockIdx.z;
    const int kh = h >> 2;
    const int tid = threadIdx.x;
    const int warp = tid >> 5, lane = tid & 31;
    const int g = lane >> 2, c = lane & 3;
    const int wrow = warp * 16;
    const float scale = 0.08838834764831845f;   // 1/sqrt(128)

    const int nkt = (qt + 1) * 4;

    // ---- Q tile: 128 rows x 16 chunks ----
    {
        const __half* gq = Qg + ((size_t)(b * SS + qt * 128) * N_HEADS + h) * HEAD_DIM;
        #pragma unroll
        for (int i = tid; i < 128 * 16; i += 256) {
            int r = i >> 4, ch = i & 15;
            cp16(sQ + (r * QSTR + ch * 8) * 2, gq + (size_t)r * N_HEADS * HEAD_DIM + ch * 8);
        }
    }
    auto kv_issue = [&](int s) {
        const int buf = s % 3;
        const __half* gk = Kg + ((size_t)(b * SS + s * KT) * N_KV_HEADS + kh) * HEAD_DIM;
        const __half* gv = Vg + ((size_t)(b * SS + s * KT) * N_KV_HEADS + kh) * HEAD_DIM;
        #pragma unroll
        for (int i = tid; i < KT * 16; i += 256) {
            int r = i >> 4, ch = i & 15;
            size_t off = (size_t)r * N_KV_HEADS * HEAD_DIM + ch * 8;
            cp16(sK + buf * KSTGB + (r * KSTR + ch * 8) * 2, gk + off);
            cp16(sV + buf * VSTGB + (r * VSTR + ch * 8) * 2, gv + off);
        }
    };
    kv_issue(0); CP_COMMIT;                 // G0: Q + stage0
    if (nkt > 1) kv_issue(1);
    CP_COMMIT;                              // G1

    float o[16][4];
    #pragma unroll
    for (int nt = 0; nt < 16; nt++)
        #pragma unroll
        for (int r = 0; r < 4; r++) o[nt][r] = 0.f;

    float m0 = -CUDART_INF_F, m1 = -CUDART_INF_F, l0 = 0.f, l1 = 0.f;
    const int r0g = qt * 128 + wrow + g;
    const int r1g = r0g + 8;

    // ldmatrix lane bases
    const uint32_t qB = sQ + (((wrow + (lane & 15)) * QSTR) + ((lane >> 4) << 3)) * 2;
    const uint32_t kB0 = sK + (((((lane >> 4) << 3) + (lane & 7)) * KSTR)
                               + (((lane >> 3) & 1) << 3)) * 2;
    const uint32_t pB = sP + (((wrow + (lane & 15)) * PSTR) + ((lane >> 4) << 3)) * 2;
    const uint32_t vB0 = sV + ((((((lane >> 3) & 1) << 3) + (lane & 7)) * VSTR)
                               + ((lane >> 4) << 3)) * 2;

    for (int jt = 0; jt < nkt; jt++) {
        CP_WAIT(1);
        __syncthreads();
        if (jt + 2 < nkt) kv_issue(jt + 2);
        CP_COMMIT;

        const int buf = jt % 3, t0 = jt * KT;
        const uint32_t kB = kB0 + buf * KSTGB;
        const uint32_t vB = vB0 + buf * VSTGB;

        // ---- S = Q K^T : 16 x 32 per warp ----
        float s4[4][4];
        #pragma unroll
        for (int ni = 0; ni < 4; ni++)
            #pragma unroll
            for (int r = 0; r < 4; r++) s4[ni][r] = 0.f;

        #pragma unroll
        for (int ks = 0; ks < 8; ks++) {
            const int kb = ks * 16;
            uint32_t qf[4];
            ldsm_x4(qf, qB + kb * 2);
            uint32_t kf[8];
            ldsm_x4(kf,     kB + kb * 2);
            ldsm_x4(kf + 4, kB + (16 * KSTR + kb) * 2);
            mma_f16(s4[0], qf, kf[0], kf[1]);
            mma_f16(s4[1], qf, kf[2], kf[3]);
            mma_f16(s4[2], qf, kf[4], kf[5]);
            mma_f16(s4[3], qf, kf[6], kf[7]);
        }

        #pragma unroll
        for (int ni = 0; ni < 4; ni++)
            #pragma unroll
            for (int r = 0; r < 4; r++) s4[ni][r] *= scale;

        if (jt >= nkt - 4) {   // diagonal blocks
            #pragma unroll
            for (int ni = 0; ni < 4; ni++) {
                int key0 = t0 + ni * 8 + 2 * c;
                if (key0 > r0g)     s4[ni][0] = -CUDART_INF_F;
                if (key0 + 1 > r0g) s4[ni][1] = -CUDART_INF_F;
                if (key0 > r1g)     s4[ni][2] = -CUDART_INF_F;
                if (key0 + 1 > r1g) s4[ni][3] = -CUDART_INF_F;
            }
        }

        // ---- online softmax ----
        float mx0 = -CUDART_INF_F, mx1 = -CUDART_INF_F;
        #pragma unroll
        for (int ni = 0; ni < 4; ni++) {
            mx0 = fmaxf(mx0, fmaxf(s4[ni][0], s4[ni][1]));
            mx1 = fmaxf(mx1, fmaxf(s4[ni][2], s4[ni][3]));
        }
        mx0 = fmaxf(mx0, __shfl_xor_sync(0xffffffffu, mx0, 1));
        mx0 = fmaxf(mx0, __shfl_xor_sync(0xffffffffu, mx0, 2));
        mx1 = fmaxf(mx1, __shfl_xor_sync(0xffffffffu, mx1, 1));
        mx1 = fmaxf(mx1, __shfl_xor_sync(0xffffffffu, mx1, 2));

        float mn0 = fmaxf(m0, mx0), mn1 = fmaxf(m1, mx1);
        float corr0 = __expf(m0 - mn0), corr1 = __expf(m1 - mn1);
        m0 = mn0; m1 = mn1;

        float ps0 = 0.f, ps1 = 0.f;
        #pragma unroll
        for (int ni = 0; ni < 4; ni++) {
            float p0 = __expf(s4[ni][0] - mn0);
            float p1 = __expf(s4[ni][1] - mn0);
            float p2 = __expf(s4[ni][2] - mn1);
            float p3 = __expf(s4[ni][3] - mn1);
            ps0 += p0 + p1;
            ps1 += p2 + p3;
            *(__half2*)&shP[(wrow + g) * PSTR + ni * 8 + 2 * c]     = __floats2half2_rn(p0, p1);
            *(__half2*)&shP[(wrow + g + 8) * PSTR + ni * 8 + 2 * c] = __floats2half2_rn(p2, p3);
        }
        ps0 += __shfl_xor_sync(0xffffffffu, ps0, 1);
        ps0 += __shfl_xor_sync(0xffffffffu, ps0, 2);
        ps1 += __shfl_xor_sync(0xffffffffu, ps1, 1);
        ps1 += __shfl_xor_sync(0xffffffffu, ps1, 2);
        l0 = l0 * corr0 + ps0;
        l1 = l1 * corr1 + ps1;

        #pragma unroll
        for (int nt = 0; nt < 16; nt++) {
            o[nt][0] *= corr0; o[nt][1] *= corr0;
            o[nt][2] *= corr1; o[nt][3] *= corr1;
        }
        __syncwarp();

        // ---- O += P V ----
        #pragma unroll
        for (int ks = 0; ks < 2; ks++) {
            const int kb = ks * 16;
            uint32_t pf[4];
            ldsm_x4(pf, pB + kb * 2);
            #pragma unroll
            for (int np = 0; np < 8; np++) {
                uint32_t vf[4];
                ldsm_x4t(vf, vB + (kb * VSTR + np * 16) * 2);
                mma_f16(o[2 * np],     pf, vf[0], vf[1]);
                mma_f16(o[2 * np + 1], pf, vf[2], vf[3]);
            }
        }
        __syncwarp();
    }

    // ---- epilogue ----
    const float inv0 = 1.f / l0, inv1 = 1.f / l1;
    #pragma unroll
    for (int nt = 0; nt < 16; nt++) {
        int col = h * HEAD_DIM + nt * 8 + 2 * c;
        *(__half2*)&Og[(size_t)(b * SS + r0g) * DIM + col] =
            __floats2half2_rn(o[nt][0] * inv0, o[nt][1] * inv0);
        *(__half2*)&Og[(size_t)(b * SS + r1g) * DIM + col] =
            __floats2half2_rn(o[nt][2] * inv1, o[nt][3] * inv1);
    }
}

// ---------------- launch ----------------
extern "C" void kernel_launch(void* const* d_in, const int* in_sizes, int n_in,
                              void* d_out, int out_size)
{
    const float* x    = (const float*)d_in[0];
    const float* fcos = (const float*)d_in[1];
    const float* fsin = (const float*)d_in[2];
    const float* wq   = (const float*)d_in[3];
    const float* wk   = (const float*)d_in[4];
    const float* wv   = (const float*)d_in[5];
    const float* wo   = (const float*)d_in[6];
    float* out = (float*)d_out;

    __half *xh, *wqh, *wkh, *wvh, *woh, *Qh, *Kh, *Vh, *Oh;
    float *Qf, *Kf;
    cudaGetSymbolAddress((void**)&xh,  g_xh);
    cudaGetSymbolAddress((void**)&wqh, g_wqh);
    cudaGetSymbolAddress((void**)&wkh, g_wkh);
    cudaGetSymbolAddress((void**)&wvh, g_wvh);
    cudaGetSymbolAddress((void**)&woh, g_woh);
    cudaGetSymbolAddress((void**)&Qf,  g_Qf);
    cudaGetSymbolAddress((void**)&Kf,  g_Kf);
    cudaGetSymbolAddress((void**)&Qh,  g_Qh);
    cudaGetSymbolAddress((void**)&Kh,  g_Kh);
    cudaGetSymbolAddress((void**)&Vh,  g_Vh);
    cudaGetSymbolAddress((void**)&Oh,  g_Oh);

    // ---- fp16 conversions ----
    {
        int n;
        n = ROWS * DIM / 2;    f2h<<<(n + 255) / 256, 256>>>(x,  xh,  n);
        n = DIM * DIM / 2;     f2h<<<(n + 255) / 256, 256>>>(wq, wqh, n);
        n = DIM * KV_DIM / 2;  f2h<<<(n + 255) / 256, 256>>>(wk, wkh, n);
        n = DIM * KV_DIM / 2;  f2h<<<(n + 255) / 256, 256>>>(wv, wvh, n);
        n = DIM * DIM / 2;     f2h<<<(n + 255) / 256, 256>>>(wo, woh, n);
    }

    const int smem_big = 4 * (128 * 40 * 2 + 32 * (256 + 8) * 2);   // 108,544
    const int smem_kv  = 4 * (128 * 40 * 2 + 32 * (128 + 8) * 2);   //  75,776
    cudaFuncSetAttribute((const void*)hgemm<256, 64, false>,
                         cudaFuncAttributeMaxDynamicSharedMemorySize, smem_big);
    cudaFuncSetAttribute((const void*)hgemm<128, 32, false>,
                         cudaFuncAttributeMaxDynamicSharedMemorySize, smem_kv);
    cudaFuncSetAttribute((const void*)hgemm<128, 32, true>,
                         cudaFuncAttributeMaxDynamicSharedMemorySize, smem_kv);
    cudaFuncSetAttribute((const void*)flash_attn,
                         cudaFuncAttributeMaxDynamicSharedMemorySize, ATTN_SMEM);

    // ---- projections ----
    hgemm<256, 64, false><<<dim3(DIM / 256, ROWS / 128), 256, smem_big>>>(xh, wqh, Qf, ROWS, DIM, DIM);
    hgemm<128, 32, false><<<dim3(KV_DIM / 128, ROWS / 128), 256, smem_kv>>>(xh, wkh, Kf, ROWS, KV_DIM, DIM);
    hgemm<128, 32, true ><<<dim3(KV_DIM / 128, ROWS / 128), 256, smem_kv>>>(xh, wvh, Vh, ROWS, KV_DIM, DIM);

    // ---- RoPE -> fp16 ----
    {
        int totQ = ROWS * N_HEADS * (HEAD_DIM / 2) / 1;   // rows*64 pairs per head row
        totQ = ROWS * N_HEADS * 64;
        int totK = ROWS * N_KV_HEADS * 64;
        rope_h<<<(totQ + 255) / 256, 256>>>(Qf, Qh, fcos, fsin, N_HEADS, totQ);
        rope_h<<<(totK + 255) / 256, 256>>>(Kf, Kh, fcos, fsin, N_KV_HEADS, totK);
    }

    // ---- attention ----
    flash_attn<<<dim3(SS / 128, N_HEADS, BB), 256, ATTN_SMEM>>>(Qh, Kh, Vh, Oh);

    // ---- output projection ----
    hgemm<256, 64, false><<<dim3(DIM / 256, ROWS / 128), 256, smem_big>>>(Oh, woh, out, ROWS, DIM, DIM);
}

// round 6
// speedup vs baseline: 10.7125x; 1.0423x over previous
#include <cuda_runtime.h>
#include <cuda_fp16.h>
#include <math_constants.h>
#include <cstdint>

#define DIM 2048
#define N_HEADS 16
#define N_KV_HEADS 4
#define HEAD_DIM 128
#define BB 2
#define SS 2048
#define ROWS (BB*SS)                  // 4096
#define KV_DIM (N_KV_HEADS*HEAD_DIM)  // 512
#define NQKV (DIM + 2*KV_DIM)         // 3072

// ---------------- static scratch (no allocations allowed) ----------------
__device__ __half g_xh  [(size_t)ROWS * DIM];
__device__ __half g_wqkv[(size_t)DIM * NQKV];
__device__ __half g_woh [(size_t)DIM * DIM];
__device__ __half g_Qh  [(size_t)ROWS * DIM];
__device__ __half g_Kh  [(size_t)ROWS * KV_DIM];
__device__ __half g_Vh  [(size_t)ROWS * KV_DIM];
__device__ __half g_Oh  [(size_t)ROWS * DIM];

// ---------------- low-level helpers ----------------
__device__ __forceinline__ uint32_t sptr(const void* p) {
    return (uint32_t)__cvta_generic_to_shared(p);
}
__device__ __forceinline__ void cp16(uint32_t dst, const void* src) {
    asm volatile("cp.async.cg.shared.global [%0], [%1], 16;\n" :: "r"(dst), "l"(src));
}
#define CP_COMMIT asm volatile("cp.async.commit_group;\n" ::: "memory")
#define CP_WAIT(N) asm volatile("cp.async.wait_group %0;\n" :: "n"(N) : "memory")

__device__ __forceinline__ void ldsm_x4(uint32_t* r, uint32_t a) {
    asm volatile("ldmatrix.sync.aligned.m8n8.x4.shared.b16 {%0,%1,%2,%3}, [%4];"
                 : "=r"(r[0]), "=r"(r[1]), "=r"(r[2]), "=r"(r[3]) : "r"(a));
}
__device__ __forceinline__ void ldsm_x4t(uint32_t* r, uint32_t a) {
    asm volatile("ldmatrix.sync.aligned.m8n8.x4.trans.shared.b16 {%0,%1,%2,%3}, [%4];"
                 : "=r"(r[0]), "=r"(r[1]), "=r"(r[2]), "=r"(r[3]) : "r"(a));
}
__device__ __forceinline__ void mma_f16(float* d, const uint32_t* a, uint32_t b0, uint32_t b1) {
    asm volatile(
        "mma.sync.aligned.m16n8k16.row.col.f32.f16.f16.f32 "
        "{%0,%1,%2,%3}, {%4,%5,%6,%7}, {%8,%9}, {%0,%1,%2,%3};"
        : "+f"(d[0]), "+f"(d[1]), "+f"(d[2]), "+f"(d[3])
        : "r"(a[0]), "r"(a[1]), "r"(a[2]), "r"(a[3]), "r"(b0), "r"(b1));
}

// ---------------- fp32 -> fp16 convert ----------------
__global__ void f2h(const float* __restrict__ in, __half* __restrict__ out, int n2) {
    int i = blockIdx.x * blockDim.x + threadIdx.x;
    if (i < n2) {
        float2 v = ((const float2*)in)[i];
        ((__half2*)out)[i] = __floats2half2_rn(v.x, v.y);
    }
}

// ---------------- concat wq|wk|wv -> fp16 [DIM][3072] ----------------
__global__ void wcat(const float* __restrict__ wq, const float* __restrict__ wk,
                     const float* __restrict__ wv, __half* __restrict__ out, int total2)
{
    int i = blockIdx.x * blockDim.x + threadIdx.x;
    if (i >= total2) return;
    int j = i * 2;
    int k = j / NQKV, n = j % NQKV;
    float2 v;
    if (n < DIM)                 v = *(const float2*)&wq[(size_t)k * DIM + n];
    else if (n < DIM + KV_DIM)   v = *(const float2*)&wk[(size_t)k * KV_DIM + (n - DIM)];
    else                         v = *(const float2*)&wv[(size_t)k * KV_DIM + (n - DIM - KV_DIM)];
    ((__half2*)out)[i] = __floats2half2_rn(v.x, v.y);
}

// ---------------- fp16 tensor-core GEMM, 4-stage cp.async --------------
// C[M,N] = A[M,K] * B[K,N]. EPI: 0 = fp32 C, 2 = fused QKV split + RoPE.
template<int BN, int WN, int EPI>
__global__ __launch_bounds__(256, 1) void hgemm(
    const __half* __restrict__ A, const __half* __restrict__ B,
    float* __restrict__ C,
    __half* __restrict__ qout, __half* __restrict__ kout, __half* __restrict__ vout,
    const float* __restrict__ cosb, const float* __restrict__ sinb,
    int M, int N, int K)
{
    constexpr int BM = 128, BK = 32, STG = 4;
    constexpr int ASTR = BK + 8;
    constexpr int BSTR = BN + 8;
    constexpr int ASZB = BM * ASTR * 2;
    constexpr int BSZB = BK * BSTR * 2;
    constexpr int NNI  = WN / 8;
    constexpr int CPB  = BN / 8;

    extern __shared__ char smem[];
    const uint32_t sA = sptr(smem);
    const uint32_t sB = sA + STG * ASZB;

    const int tid = threadIdx.x, warp = tid >> 5, lane = tid & 31;
    const int g = lane >> 2, c = lane & 3;
    const int wm = (warp & 1) * 64, wn = (warp >> 1) * WN;
    const int bm = blockIdx.y * BM, bn = blockIdx.x * BN;

    auto issue = [&](int kt) {
        const int st = kt & (STG - 1);
        const uint32_t da = sA + st * ASZB;
        const __half* ga = A + (size_t)bm * K + (size_t)kt * BK;
        #pragma unroll
        for (int i = tid; i < 128 * 4; i += 256) {
            int r = i >> 2, ch = i & 3;
            cp16(da + (r * ASTR + ch * 8) * 2, ga + (size_t)r * K + ch * 8);
        }
        const uint32_t db = sB + st * BSZB;
        const __half* gb = B + (size_t)kt * BK * N + bn;
        #pragma unroll
        for (int i = tid; i < 32 * CPB; i += 256) {
            int r = i / CPB, ch = i % CPB;
            cp16(db + (r * BSTR + ch * 8) * 2, gb + (size_t)r * N + ch * 8);
        }
    };

    issue(0); CP_COMMIT;
    issue(1); CP_COMMIT;
    issue(2); CP_COMMIT;

    float acc[4][NNI][4];
    #pragma unroll
    for (int mi = 0; mi < 4; mi++)
        #pragma unroll
        for (int ni = 0; ni < NNI; ni++)
            #pragma unroll
            for (int r = 0; r < 4; r++) acc[mi][ni][r] = 0.f;

    const uint32_t aBase = sA + (((wm + (lane & 15)) * ASTR) + ((lane >> 4) << 3)) * 2;
    const uint32_t bBase = sB + (((((lane >> 3) & 1) * 8 + (lane & 7)) * BSTR)
                                 + wn + ((lane >> 4) << 3)) * 2;

    const int NT = K / BK;
    for (int kt = 0; kt < NT; kt++) {
        CP_WAIT(2);
        __syncthreads();
        if (kt + 3 < NT) issue(kt + 3);
        CP_COMMIT;

        const int st = kt & (STG - 1);
        const uint32_t ab = aBase + st * ASZB;
        const uint32_t bb = bBase + st * BSZB;

        #pragma unroll
        for (int kk = 0; kk < 2; kk++) {
            const int kb = kk * 16;
            uint32_t af[4][4];
            #pragma unroll
            for (int mi = 0; mi < 4; mi++)
                ldsm_x4(af[mi], ab + (mi * 16 * ASTR + kb) * 2);
            uint32_t bf[NNI][2];
            #pragma unroll
            for (int nip = 0; nip < NNI / 2; nip++) {
                uint32_t t[4];
                ldsm_x4t(t, bb + (kb * BSTR + nip * 16) * 2);
                bf[2 * nip][0] = t[0]; bf[2 * nip][1] = t[1];
                bf[2 * nip + 1][0] = t[2]; bf[2 * nip + 1][1] = t[3];
            }
            #pragma unroll
            for (int mi = 0; mi < 4; mi++)
                #pragma unroll
                for (int ni = 0; ni < NNI; ni++)
                    mma_f16(acc[mi][ni], af[mi], bf[ni][0], bf[ni][1]);
        }
    }

    // ---- epilogue ----
    #pragma unroll
    for (int mi = 0; mi < 4; mi++) {
        const int r0 = bm + wm + mi * 16 + g;
        const int r1 = r0 + 8;
        #pragma unroll
        for (int ni = 0; ni < NNI; ni++) {
            const int col = bn + wn + ni * 8 + 2 * c;
            float v0 = acc[mi][ni][0], v1 = acc[mi][ni][1];
            float v2 = acc[mi][ni][2], v3 = acc[mi][ni][3];
            if (EPI == 0) {
                *(float2*)&C[(size_t)r0 * N + col] = make_float2(v0, v1);
                *(float2*)&C[(size_t)r1 * N + col] = make_float2(v2, v3);
            } else {
                const int s0 = r0 & (SS - 1), s1 = r1 & (SS - 1);
                if (col < DIM) {                      // Q + RoPE
                    const int d2 = (col & 127) >> 1;
                    float c0 = cosb[s0 * 64 + d2], n0 = sinb[s0 * 64 + d2];
                    float c1 = cosb[s1 * 64 + d2], n1 = sinb[s1 * 64 + d2];
                    *(__half2*)&qout[(size_t)r0 * DIM + col] =
                        __floats2half2_rn(v0 * c0 - v1 * n0, v0 * n0 + v1 * c0);
                    *(__half2*)&qout[(size_t)r1 * DIM + col] =
                        __floats2half2_rn(v2 * c1 - v3 * n1, v2 * n1 + v3 * c1);
                } else if (col < DIM + KV_DIM) {      // K + RoPE
                    const int cc = col - DIM;
                    const int d2 = (cc & 127) >> 1;
                    float c0 = cosb[s0 * 64 + d2], n0 = sinb[s0 * 64 + d2];
                    float c1 = cosb[s1 * 64 + d2], n1 = sinb[s1 * 64 + d2];
                    *(__half2*)&kout[(size_t)r0 * KV_DIM + cc] =
                        __floats2half2_rn(v0 * c0 - v1 * n0, v0 * n0 + v1 * c0);
                    *(__half2*)&kout[(size_t)r1 * KV_DIM + cc] =
                        __floats2half2_rn(v2 * c1 - v3 * n1, v2 * n1 + v3 * c1);
                } else {                              // V
                    const int cc = col - DIM - KV_DIM;
                    *(__half2*)&vout[(size_t)r0 * KV_DIM + cc] = __floats2half2_rn(v0, v1);
                    *(__half2*)&vout[(size_t)r1 * KV_DIM + cc] = __floats2half2_rn(v2, v3);
                }
            }
        }
    }
}

// ---------------- FlashAttention fp16, 3-stage cp.async K/V -------------
#define KT   32
#define QSTR 136
#define KSTR 136
#define VSTR 136
#define PSTR 40
#define KSTGB (KT*KSTR*2)
#define VSTGB (KT*VSTR*2)
#define ATTN_SMEM ((128*QSTR + 3*KT*KSTR + 3*KT*VSTR + 128*PSTR) * 2)

__global__ __launch_bounds__(256, 2) void flash_attn(
    const __half* __restrict__ Qg, const __half* __restrict__ Kg,
    const __half* __restrict__ Vg, __half* __restrict__ Og)
{
    extern __shared__ char smem[];
    __half* shQ = (__half*)smem;
    __half* shK = shQ + 128 * QSTR;
    __half* shV = shK + 3 * KT * KSTR;
    __half* shP = shV + 3 * KT * VSTR;
    const uint32_t sQ = sptr(shQ), sK = sptr(shK), sV = sptr(shV), sP = sptr(shP);

    const int qt = blockIdx.x, h = blockIdx.y, b = blockIdx.z;
    const int kh = h >> 2;
    const int tid = threadIdx.x;
    const int warp = tid >> 5, lane = tid & 31;
    const int g = lane >> 2, c = lane & 3;
    const int wrow = warp * 16;
    const float scale = 0.08838834764831845f;

    const int nkt = (qt + 1) * 4;

    {
        const __half* gq = Qg + ((size_t)(b * SS + qt * 128) * N_HEADS + h) * HEAD_DIM;
        #pragma unroll
        for (int i = tid; i < 128 * 16; i += 256) {
            int r = i >> 4, ch = i & 15;
            cp16(sQ + (r * QSTR + ch * 8) * 2, gq + (size_t)r * N_HEADS * HEAD_DIM + ch * 8);
        }
    }
    auto kv_issue = [&](int s) {
        const int buf = s % 3;
        const __half* gk = Kg + ((size_t)(b * SS + s * KT) * N_KV_HEADS + kh) * HEAD_DIM;
        const __half* gv = Vg + ((size_t)(b * SS + s * KT) * N_KV_HEADS + kh) * HEAD_DIM;
        #pragma unroll
        for (int i = tid; i < KT * 16; i += 256) {
            int r = i >> 4, ch = i & 15;
            size_t off = (size_t)r * N_KV_HEADS * HEAD_DIM + ch * 8;
            cp16(sK + buf * KSTGB + (r * KSTR + ch * 8) * 2, gk + off);
            cp16(sV + buf * VSTGB + (r * VSTR + ch * 8) * 2, gv + off);
        }
    };
    kv_issue(0); CP_COMMIT;
    if (nkt > 1) kv_issue(1);
    CP_COMMIT;

    float o[16][4];
    #pragma unroll
    for (int nt = 0; nt < 16; nt++)
        #pragma unroll
        for (int r = 0; r < 4; r++) o[nt][r] = 0.f;

    float m0 = -CUDART_INF_F, m1 = -CUDART_INF_F, l0 = 0.f, l1 = 0.f;
    const int r0g = qt * 128 + wrow + g;
    const int r1g = r0g + 8;

    const uint32_t qB = sQ + (((wrow + (lane & 15)) * QSTR) + ((lane >> 4) << 3)) * 2;
    const uint32_t kB0 = sK + (((((lane >> 4) << 3) + (lane & 7)) * KSTR)
                               + (((lane >> 3) & 1) << 3)) * 2;
    const uint32_t pB = sP + (((wrow + (lane & 15)) * PSTR) + ((lane >> 4) << 3)) * 2;
    const uint32_t vB0 = sV + ((((((lane >> 3) & 1) << 3) + (lane & 7)) * VSTR)
                               + ((lane >> 4) << 3)) * 2;

    for (int jt = 0; jt < nkt; jt++) {
        CP_WAIT(1);
        __syncthreads();
        if (jt + 2 < nkt) kv_issue(jt + 2);
        CP_COMMIT;

        const int buf = jt % 3, t0 = jt * KT;
        const uint32_t kB = kB0 + buf * KSTGB;
        const uint32_t vB = vB0 + buf * VSTGB;

        float s4[4][4];
        #pragma unroll
        for (int ni = 0; ni < 4; ni++)
            #pragma unroll
            for (int r = 0; r < 4; r++) s4[ni][r] = 0.f;

        #pragma unroll
        for (int ks = 0; ks < 8; ks++) {
            const int kb = ks * 16;
            uint32_t qf[4];
            ldsm_x4(qf, qB + kb * 2);
            uint32_t kf[8];
            ldsm_x4(kf,     kB + kb * 2);
            ldsm_x4(kf + 4, kB + (16 * KSTR + kb) * 2);
            mma_f16(s4[0], qf, kf[0], kf[1]);
            mma_f16(s4[1], qf, kf[2], kf[3]);
            mma_f16(s4[2], qf, kf[4], kf[5]);
            mma_f16(s4[3], qf, kf[6], kf[7]);
        }

        #pragma unroll
        for (int ni = 0; ni < 4; ni++)
            #pragma unroll
            for (int r = 0; r < 4; r++) s4[ni][r] *= scale;

        if (jt >= nkt - 4) {
            #pragma unroll
            for (int ni = 0; ni < 4; ni++) {
                int key0 = t0 + ni * 8 + 2 * c;
                if (key0 > r0g)     s4[ni][0] = -CUDART_INF_F;
                if (key0 + 1 > r0g) s4[ni][1] = -CUDART_INF_F;
                if (key0 > r1g)     s4[ni][2] = -CUDART_INF_F;
                if (key0 + 1 > r1g) s4[ni][3] = -CUDART_INF_F;
            }
        }

        float mx0 = -CUDART_INF_F, mx1 = -CUDART_INF_F;
        #pragma unroll
        for (int ni = 0; ni < 4; ni++) {
            mx0 = fmaxf(mx0, fmaxf(s4[ni][0], s4[ni][1]));
            mx1 = fmaxf(mx1, fmaxf(s4[ni][2], s4[ni][3]));
        }
        mx0 = fmaxf(mx0, __shfl_xor_sync(0xffffffffu, mx0, 1));
        mx0 = fmaxf(mx0, __shfl_xor_sync(0xffffffffu, mx0, 2));
        mx1 = fmaxf(mx1, __shfl_xor_sync(0xffffffffu, mx1, 1));
        mx1 = fmaxf(mx1, __shfl_xor_sync(0xffffffffu, mx1, 2));

        float mn0 = fmaxf(m0, mx0), mn1 = fmaxf(m1, mx1);
        float corr0 = __expf(m0 - mn0), corr1 = __expf(m1 - mn1);
        m0 = mn0; m1 = mn1;

        float ps0 = 0.f, ps1 = 0.f;
        #pragma unroll
        for (int ni = 0; ni < 4; ni++) {
            float p0 = __expf(s4[ni][0] - mn0);
            float p1 = __expf(s4[ni][1] - mn0);
            float p2 = __expf(s4[ni][2] - mn1);
            float p3 = __expf(s4[ni][3] - mn1);
            ps0 += p0 + p1;
            ps1 += p2 + p3;
            *(__half2*)&shP[(wrow + g) * PSTR + ni * 8 + 2 * c]     = __floats2half2_rn(p0, p1);
            *(__half2*)&shP[(wrow + g + 8) * PSTR + ni * 8 + 2 * c] = __floats2half2_rn(p2, p3);
        }
        ps0 += __shfl_xor_sync(0xffffffffu, ps0, 1);
        ps0 += __shfl_xor_sync(0xffffffffu, ps0, 2);
        ps1 += __shfl_xor_sync(0xffffffffu, ps1, 1);
        ps1 += __shfl_xor_sync(0xffffffffu, ps1, 2);
        l0 = l0 * corr0 + ps0;
        l1 = l1 * corr1 + ps1;

        #pragma unroll
        for (int nt = 0; nt < 16; nt++) {
            o[nt][0] *= corr0; o[nt][1] *= corr0;
            o[nt][2] *= corr1; o[nt][3] *= corr1;
        }
        __syncwarp();

        #pragma unroll
        for (int ks = 0; ks < 2; ks++) {
            const int kb = ks * 16;
            uint32_t pf[4];
            ldsm_x4(pf, pB + kb * 2);
            #pragma unroll
            for (int np = 0; np < 8; np++) {
                uint32_t vf[4];
                ldsm_x4t(vf, vB + (kb * VSTR + np * 16) * 2);
                mma_f16(o[2 * np],     pf, vf[0], vf[1]);
                mma_f16(o[2 * np + 1], pf, vf[2], vf[3]);
            }
        }
        __syncwarp();
    }

    const float inv0 = 1.f / l0, inv1 = 1.f / l1;
    #pragma unroll
    for (int nt = 0; nt < 16; nt++) {
        int col = h * HEAD_DIM + nt * 8 + 2 * c;
        *(__half2*)&Og[(size_t)(b * SS + r0g) * DIM + col] =
            __floats2half2_rn(o[nt][0] * inv0, o[nt][1] * inv0);
        *(__half2*)&Og[(size_t)(b * SS + r1g) * DIM + col] =
            __floats2half2_rn(o[nt][2] * inv1, o[nt][3] * inv1);
    }
}

// ---------------- launch ----------------
extern "C" void kernel_launch(void* const* d_in, const int* in_sizes, int n_in,
                              void* d_out, int out_size)
{
    const float* x    = (const float*)d_in[0];
    const float* fcos = (const float*)d_in[1];
    const float* fsin = (const float*)d_in[2];
    const float* wq   = (const float*)d_in[3];
    const float* wk   = (const float*)d_in[4];
    const float* wv   = (const float*)d_in[5];
    const float* wo   = (const float*)d_in[6];
    float* out = (float*)d_out;

    __half *xh, *wqkvh, *woh, *Qh, *Kh, *Vh, *Oh;
    cudaGetSymbolAddress((void**)&xh,    g_xh);
    cudaGetSymbolAddress((void**)&wqkvh, g_wqkv);
    cudaGetSymbolAddress((void**)&woh,   g_woh);
    cudaGetSymbolAddress((void**)&Qh,    g_Qh);
    cudaGetSymbolAddress((void**)&Kh,    g_Kh);
    cudaGetSymbolAddress((void**)&Vh,    g_Vh);
    cudaGetSymbolAddress((void**)&Oh,    g_Oh);

    // ---- conversions ----
    {
        int n = ROWS * DIM / 2;
        f2h<<<(n + 255) / 256, 256>>>(x, xh, n);
        int n2 = DIM * NQKV / 2;
        wcat<<<(n2 + 255) / 256, 256>>>(wq, wk, wv, wqkvh, n2);
        int n3 = DIM * DIM / 2;
        f2h<<<(n3 + 255) / 256, 256>>>(wo, woh, n3);
    }

    const int smem_big = 4 * (128 * 40 * 2 + 32 * (256 + 8) * 2);   // 108,544
    cudaFuncSetAttribute((const void*)hgemm<256, 64, 2>,
                         cudaFuncAttributeMaxDynamicSharedMemorySize, smem_big);
    cudaFuncSetAttribute((const void*)hgemm<256, 64, 0>,
                         cudaFuncAttributeMaxDynamicSharedMemorySize, smem_big);
    cudaFuncSetAttribute((const void*)flash_attn,
                         cudaFuncAttributeMaxDynamicSharedMemorySize, ATTN_SMEM);

    // ---- fused QKV projection + RoPE + fp16 store ----
    hgemm<256, 64, 2><<<dim3(NQKV / 256, ROWS / 128), 256, smem_big>>>(
        xh, wqkvh, nullptr, Qh, Kh, Vh, fcos, fsin, ROWS, NQKV, DIM);

    // ---- attention ----
    flash_attn<<<dim3(SS / 128, N_HEADS, BB), 256, ATTN_SMEM>>>(Qh, Kh, Vh, Oh);

    // ---- output projection (fp32 out) ----
    hgemm<256, 64, 0><<<dim3(DIM / 256, ROWS / 128), 256, smem_big>>>(
        Oh, woh, out, nullptr, nullptr, nullptr, nullptr, nullptr, ROWS, DIM, DIM);
}

// round 7
// speedup vs baseline: 11.8191x; 1.1033x over previous
#include <cuda_runtime.h>
#include <cuda_fp16.h>
#include <math_constants.h>
#include <cstdint>

#define DIM 2048
#define N_HEADS 16
#define N_KV_HEADS 4
#define HEAD_DIM 128
#define BB 2
#define SS 2048
#define ROWS (BB*SS)                  // 4096
#define KV_DIM (N_KV_HEADS*HEAD_DIM)  // 512
#define NQKV (DIM + 2*KV_DIM)         // 3072

// ---------------- static scratch (no allocations allowed) ----------------
__device__ __half g_xh  [(size_t)ROWS * DIM];
__device__ __half g_wqkv[(size_t)DIM * NQKV];
__device__ __half g_woh [(size_t)DIM * DIM];
__device__ __half g_Qh  [(size_t)ROWS * DIM];
__device__ __half g_Kh  [(size_t)ROWS * KV_DIM];
__device__ __half g_Vh  [(size_t)ROWS * KV_DIM];
__device__ __half g_Oh  [(size_t)ROWS * DIM];

// ---------------- low-level helpers ----------------
__device__ __forceinline__ uint32_t sptr(const void* p) {
    return (uint32_t)__cvta_generic_to_shared(p);
}
__device__ __forceinline__ void cp16(uint32_t dst, const void* src) {
    asm volatile("cp.async.cg.shared.global [%0], [%1], 16;\n" :: "r"(dst), "l"(src));
}
#define CP_COMMIT asm volatile("cp.async.commit_group;\n" ::: "memory")
#define CP_WAIT(N) asm volatile("cp.async.wait_group %0;\n" :: "n"(N) : "memory")

__device__ __forceinline__ void ldsm_x4(uint32_t* r, uint32_t a) {
    asm volatile("ldmatrix.sync.aligned.m8n8.x4.shared.b16 {%0,%1,%2,%3}, [%4];"
                 : "=r"(r[0]), "=r"(r[1]), "=r"(r[2]), "=r"(r[3]) : "r"(a));
}
__device__ __forceinline__ void ldsm_x4t(uint32_t* r, uint32_t a) {
    asm volatile("ldmatrix.sync.aligned.m8n8.x4.trans.shared.b16 {%0,%1,%2,%3}, [%4];"
                 : "=r"(r[0]), "=r"(r[1]), "=r"(r[2]), "=r"(r[3]) : "r"(a));
}
__device__ __forceinline__ void mma_f16(float* d, const uint32_t* a, uint32_t b0, uint32_t b1) {
    asm volatile(
        "mma.sync.aligned.m16n8k16.row.col.f32.f16.f16.f32 "
        "{%0,%1,%2,%3}, {%4,%5,%6,%7}, {%8,%9}, {%0,%1,%2,%3};"
        : "+f"(d[0]), "+f"(d[1]), "+f"(d[2]), "+f"(d[3])
        : "r"(a[0]), "r"(a[1]), "r"(a[2]), "r"(a[3]), "r"(b0), "r"(b1));
}

// ---------------- fp32 -> fp16 convert ----------------
__global__ void f2h(const float* __restrict__ in, __half* __restrict__ out, int n2) {
    int i = blockIdx.x * blockDim.x + threadIdx.x;
    if (i < n2) {
        float2 v = ((const float2*)in)[i];
        ((__half2*)out)[i] = __floats2half2_rn(v.x, v.y);
    }
}

// ---------------- concat wq|wk|wv -> fp16 [DIM][3072] ----------------
__global__ void wcat(const float* __restrict__ wq, const float* __restrict__ wk,
                     const float* __restrict__ wv, __half* __restrict__ out, int total2)
{
    int i = blockIdx.x * blockDim.x + threadIdx.x;
    if (i >= total2) return;
    int j = i * 2;
    int k = j / NQKV, n = j % NQKV;
    float2 v;
    if (n < DIM)                 v = *(const float2*)&wq[(size_t)k * DIM + n];
    else if (n < DIM + KV_DIM)   v = *(const float2*)&wk[(size_t)k * KV_DIM + (n - DIM)];
    else                         v = *(const float2*)&wv[(size_t)k * KV_DIM + (n - DIM - KV_DIM)];
    ((__half2*)out)[i] = __floats2half2_rn(v.x, v.y);
}

// ---------------- fp16 GEMM: 128x128x32, 4-stage, 2 CTAs/SM --------------
// C[M,N] = A[M,K] * B[K,N]. EPI: 0 = fp32 C, 2 = fused QKV split + RoPE.
// 256 threads, warps 2x4, warp tile 64x32.
template<int EPI>
__global__ __launch_bounds__(256, 2) void hgemm(
    const __half* __restrict__ A, const __half* __restrict__ B,
    float* __restrict__ C,
    __half* __restrict__ qout, __half* __restrict__ kout, __half* __restrict__ vout,
    const float* __restrict__ cosb, const float* __restrict__ sinb,
    int M, int N, int K)
{
    constexpr int BM = 128, BN = 128, BK = 32, STG = 4;
    constexpr int ASTR = BK + 8;           // 40 halves
    constexpr int BSTR = BN + 8;           // 136 halves
    constexpr int ASZB = BM * ASTR * 2;    // 10240
    constexpr int BSZB = BK * BSTR * 2;    // 8704
    constexpr int NNI  = 4;                // WN/8
    constexpr int CPB  = BN / 8;           // 16

    extern __shared__ char smem[];
    const uint32_t sA = sptr(smem);
    const uint32_t sB = sA + STG * ASZB;

    const int tid = threadIdx.x, warp = tid >> 5, lane = tid & 31;
    const int g = lane >> 2, c = lane & 3;
    const int wm = (warp & 1) * 64, wn = (warp >> 1) * 32;
    const int bm = blockIdx.y * BM, bn = blockIdx.x * BN;

    auto issue = [&](int kt) {
        const int st = kt & (STG - 1);
        const uint32_t da = sA + st * ASZB;
        const __half* ga = A + (size_t)bm * K + (size_t)kt * BK;
        #pragma unroll
        for (int i = tid; i < 128 * 4; i += 256) {
            int r = i >> 2, ch = i & 3;
            cp16(da + (r * ASTR + ch * 8) * 2, ga + (size_t)r * K + ch * 8);
        }
        const uint32_t db = sB + st * BSZB;
        const __half* gb = B + (size_t)kt * BK * N + bn;
        #pragma unroll
        for (int i = tid; i < 32 * CPB; i += 256) {
            int r = i / CPB, ch = i % CPB;
            cp16(db + (r * BSTR + ch * 8) * 2, gb + (size_t)r * N + ch * 8);
        }
    };

    issue(0); CP_COMMIT;
    issue(1); CP_COMMIT;
    issue(2); CP_COMMIT;

    float acc[4][NNI][4];
    #pragma unroll
    for (int mi = 0; mi < 4; mi++)
        #pragma unroll
        for (int ni = 0; ni < NNI; ni++)
            #pragma unroll
            for (int r = 0; r < 4; r++) acc[mi][ni][r] = 0.f;

    const uint32_t aBase = sA + (((wm + (lane & 15)) * ASTR) + ((lane >> 4) << 3)) * 2;
    const uint32_t bBase = sB + (((((lane >> 3) & 1) * 8 + (lane & 7)) * BSTR)
                                 + wn + ((lane >> 4) << 3)) * 2;

    const int NT = K / BK;
    for (int kt = 0; kt < NT; kt++) {
        CP_WAIT(2);
        __syncthreads();
        if (kt + 3 < NT) issue(kt + 3);
        CP_COMMIT;

        const int st = kt & (STG - 1);
        const uint32_t ab = aBase + st * ASZB;
        const uint32_t bb = bBase + st * BSZB;

        #pragma unroll
        for (int kk = 0; kk < 2; kk++) {
            const int kb = kk * 16;
            uint32_t af[4][4];
            #pragma unroll
            for (int mi = 0; mi < 4; mi++)
                ldsm_x4(af[mi], ab + (mi * 16 * ASTR + kb) * 2);
            uint32_t bf[NNI][2];
            #pragma unroll
            for (int nip = 0; nip < NNI / 2; nip++) {
                uint32_t t[4];
                ldsm_x4t(t, bb + (kb * BSTR + nip * 16) * 2);
                bf[2 * nip][0] = t[0]; bf[2 * nip][1] = t[1];
                bf[2 * nip + 1][0] = t[2]; bf[2 * nip + 1][1] = t[3];
            }
            #pragma unroll
            for (int mi = 0; mi < 4; mi++)
                #pragma unroll
                for (int ni = 0; ni < NNI; ni++)
                    mma_f16(acc[mi][ni], af[mi], bf[ni][0], bf[ni][1]);
        }
    }

    // ---- epilogue ----
    #pragma unroll
    for (int mi = 0; mi < 4; mi++) {
        const int r0 = bm + wm + mi * 16 + g;
        const int r1 = r0 + 8;
        #pragma unroll
        for (int ni = 0; ni < NNI; ni++) {
            const int col = bn + wn + ni * 8 + 2 * c;
            float v0 = acc[mi][ni][0], v1 = acc[mi][ni][1];
            float v2 = acc[mi][ni][2], v3 = acc[mi][ni][3];
            if (EPI == 0) {
                *(float2*)&C[(size_t)r0 * N + col] = make_float2(v0, v1);
                *(float2*)&C[(size_t)r1 * N + col] = make_float2(v2, v3);
            } else {
                const int s0 = r0 & (SS - 1), s1 = r1 & (SS - 1);
                if (col < DIM) {                      // Q + RoPE
                    const int d2 = (col & 127) >> 1;
                    float c0 = cosb[s0 * 64 + d2], n0 = sinb[s0 * 64 + d2];
                    float c1 = cosb[s1 * 64 + d2], n1 = sinb[s1 * 64 + d2];
                    *(__half2*)&qout[(size_t)r0 * DIM + col] =
                        __floats2half2_rn(v0 * c0 - v1 * n0, v0 * n0 + v1 * c0);
                    *(__half2*)&qout[(size_t)r1 * DIM + col] =
                        __floats2half2_rn(v2 * c1 - v3 * n1, v2 * n1 + v3 * c1);
                } else if (col < DIM + KV_DIM) {      // K + RoPE
                    const int cc = col - DIM;
                    const int d2 = (cc & 127) >> 1;
                    float c0 = cosb[s0 * 64 + d2], n0 = sinb[s0 * 64 + d2];
                    float c1 = cosb[s1 * 64 + d2], n1 = sinb[s1 * 64 + d2];
                    *(__half2*)&kout[(size_t)r0 * KV_DIM + cc] =
                        __floats2half2_rn(v0 * c0 - v1 * n0, v0 * n0 + v1 * c0);
                    *(__half2*)&kout[(size_t)r1 * KV_DIM + cc] =
                        __floats2half2_rn(v2 * c1 - v3 * n1, v2 * n1 + v3 * c1);
                } else {                              // V
                    const int cc = col - DIM - KV_DIM;
                    *(__half2*)&vout[(size_t)r0 * KV_DIM + cc] = __floats2half2_rn(v0, v1);
                    *(__half2*)&vout[(size_t)r1 * KV_DIM + cc] = __floats2half2_rn(v2, v3);
                }
            }
        }
    }
}

// ---------------- FlashAttention fp16, 3-stage cp.async K/V -------------
#define KT   32
#define QSTR 136
#define KSTR 136
#define VSTR 136
#define PSTR 40
#define KSTGB (KT*KSTR*2)
#define VSTGB (KT*VSTR*2)
#define ATTN_SMEM ((128*QSTR + 3*KT*KSTR + 3*KT*VSTR + 128*PSTR) * 2)

__global__ __launch_bounds__(256, 2) void flash_attn(
    const __half* __restrict__ Qg, const __half* __restrict__ Kg,
    const __half* __restrict__ Vg, __half* __restrict__ Og)
{
    extern __shared__ char smem[];
    __half* shQ = (__half*)smem;
    __half* shK = shQ + 128 * QSTR;
    __half* shV = shK + 3 * KT * KSTR;
    __half* shP = shV + 3 * KT * VSTR;
    const uint32_t sQ = sptr(shQ), sK = sptr(shK), sV = sptr(shV), sP = sptr(shP);

    const int qt = blockIdx.x, h = blockIdx.y, b = blockIdx.z;
    const int kh = h >> 2;
    const int tid = threadIdx.x;
    const int warp = tid >> 5, lane = tid & 31;
    const int g = lane >> 2, c = lane & 3;
    const int wrow = warp * 16;
    const float scale = 0.08838834764831845f;

    const int nkt = (qt + 1) * 4;

    {
        const __half* gq = Qg + ((size_t)(b * SS + qt * 128) * N_HEADS + h) * HEAD_DIM;
        #pragma unroll
        for (int i = tid; i < 128 * 16; i += 256) {
            int r = i >> 4, ch = i & 15;
            cp16(sQ + (r * QSTR + ch * 8) * 2, gq + (size_t)r * N_HEADS * HEAD_DIM + ch * 8);
        }
    }
    auto kv_issue = [&](int s) {
        const int buf = s % 3;
        const __half* gk = Kg + ((size_t)(b * SS + s * KT) * N_KV_HEADS + kh) * HEAD_DIM;
        const __half* gv = Vg + ((size_t)(b * SS + s * KT) * N_KV_HEADS + kh) * HEAD_DIM;
        #pragma unroll
        for (int i = tid; i < KT * 16; i += 256) {
            int r = i >> 4, ch = i & 15;
            size_t off = (size_t)r * N_KV_HEADS * HEAD_DIM + ch * 8;
            cp16(sK + buf * KSTGB + (r * KSTR + ch * 8) * 2, gk + off);
            cp16(sV + buf * VSTGB + (r * VSTR + ch * 8) * 2, gv + off);
        }
    };
    kv_issue(0); CP_COMMIT;
    if (nkt > 1) kv_issue(1);
    CP_COMMIT;

    float o[16][4];
    #pragma unroll
    for (int nt = 0; nt < 16; nt++)
        #pragma unroll
        for (int r = 0; r < 4; r++) o[nt][r] = 0.f;

    float m0 = -CUDART_INF_F, m1 = -CUDART_INF_F, l0 = 0.f, l1 = 0.f;
    const int r0g = qt * 128 + wrow + g;
    const int r1g = r0g + 8;

    const uint32_t qB = sQ + (((wrow + (lane & 15)) * QSTR) + ((lane >> 4) << 3)) * 2;
    const uint32_t kB0 = sK + (((((lane >> 4) << 3) + (lane & 7)) * KSTR)
                               + (((lane >> 3) & 1) << 3)) * 2;
    const uint32_t pB = sP + (((wrow + (lane & 15)) * PSTR) + ((lane >> 4) << 3)) * 2;
    const uint32_t vB0 = sV + ((((((lane >> 3) & 1) << 3) + (lane & 7)) * VSTR)
                               + ((lane >> 4) << 3)) * 2;

    for (int jt = 0; jt < nkt; jt++) {
        CP_WAIT(1);
        __syncthreads();
        if (jt + 2 < nkt) kv_issue(jt + 2);
        CP_COMMIT;

        const int buf = jt % 3, t0 = jt * KT;
        const uint32_t kB = kB0 + buf * KSTGB;
        const uint32_t vB = vB0 + buf * VSTGB;

        float s4[4][4];
        #pragma unroll
        for (int ni = 0; ni < 4; ni++)
            #pragma unroll
            for (int r = 0; r < 4; r++) s4[ni][r] = 0.f;

        #pragma unroll
        for (int ks = 0; ks < 8; ks++) {
            const int kb = ks * 16;
            uint32_t qf[4];
            ldsm_x4(qf, qB + kb * 2);
            uint32_t kf[8];
            ldsm_x4(kf,     kB + kb * 2);
            ldsm_x4(kf + 4, kB + (16 * KSTR + kb) * 2);
            mma_f16(s4[0], qf, kf[0], kf[1]);
            mma_f16(s4[1], qf, kf[2], kf[3]);
            mma_f16(s4[2], qf, kf[4], kf[5]);
            mma_f16(s4[3], qf, kf[6], kf[7]);
        }

        #pragma unroll
        for (int ni = 0; ni < 4; ni++)
            #pragma unroll
            for (int r = 0; r < 4; r++) s4[ni][r] *= scale;

        if (jt >= nkt - 4) {
            #pragma unroll
            for (int ni = 0; ni < 4; ni++) {
                int key0 = t0 + ni * 8 + 2 * c;
                if (key0 > r0g)     s4[ni][0] = -CUDART_INF_F;
                if (key0 + 1 > r0g) s4[ni][1] = -CUDART_INF_F;
                if (key0 > r1g)     s4[ni][2] = -CUDART_INF_F;
                if (key0 + 1 > r1g) s4[ni][3] = -CUDART_INF_F;
            }
        }

        float mx0 = -CUDART_INF_F, mx1 = -CUDART_INF_F;
        #pragma unroll
        for (int ni = 0; ni < 4; ni++) {
            mx0 = fmaxf(mx0, fmaxf(s4[ni][0], s4[ni][1]));
            mx1 = fmaxf(mx1, fmaxf(s4[ni][2], s4[ni][3]));
        }
        mx0 = fmaxf(mx0, __shfl_xor_sync(0xffffffffu, mx0, 1));
        mx0 = fmaxf(mx0, __shfl_xor_sync(0xffffffffu, mx0, 2));
        mx1 = fmaxf(mx1, __shfl_xor_sync(0xffffffffu, mx1, 1));
        mx1 = fmaxf(mx1, __shfl_xor_sync(0xffffffffu, mx1, 2));

        float mn0 = fmaxf(m0, mx0), mn1 = fmaxf(m1, mx1);
        float corr0 = __expf(m0 - mn0), corr1 = __expf(m1 - mn1);
        m0 = mn0; m1 = mn1;

        float ps0 = 0.f, ps1 = 0.f;
        #pragma unroll
        for (int ni = 0; ni < 4; ni++) {
            float p0 = __expf(s4[ni][0] - mn0);
            float p1 = __expf(s4[ni][1] - mn0);
            float p2 = __expf(s4[ni][2] - mn1);
            float p3 = __expf(s4[ni][3] - mn1);
            ps0 += p0 + p1;
            ps1 += p2 + p3;
            *(__half2*)&shP[(wrow + g) * PSTR + ni * 8 + 2 * c]     = __floats2half2_rn(p0, p1);
            *(__half2*)&shP[(wrow + g + 8) * PSTR + ni * 8 + 2 * c] = __floats2half2_rn(p2, p3);
        }
        ps0 += __shfl_xor_sync(0xffffffffu, ps0, 1);
        ps0 += __shfl_xor_sync(0xffffffffu, ps0, 2);
        ps1 += __shfl_xor_sync(0xffffffffu, ps1, 1);
        ps1 += __shfl_xor_sync(0xffffffffu, ps1, 2);
        l0 = l0 * corr0 + ps0;
        l1 = l1 * corr1 + ps1;

        #pragma unroll
        for (int nt = 0; nt < 16; nt++) {
            o[nt][0] *= corr0; o[nt][1] *= corr0;
            o[nt][2] *= corr1; o[nt][3] *= corr1;
        }
        __syncwarp();

        #pragma unroll
        for (int ks = 0; ks < 2; ks++) {
            const int kb = ks * 16;
            uint32_t pf[4];
            ldsm_x4(pf, pB + kb * 2);
            #pragma unroll
            for (int np = 0; np < 8; np++) {
                uint32_t vf[4];
                ldsm_x4t(vf, vB + (kb * VSTR + np * 16) * 2);
                mma_f16(o[2 * np],     pf, vf[0], vf[1]);
                mma_f16(o[2 * np + 1], pf, vf[2], vf[3]);
            }
        }
        __syncwarp();
    }

    const float inv0 = 1.f / l0, inv1 = 1.f / l1;
    #pragma unroll
    for (int nt = 0; nt < 16; nt++) {
        int col = h * HEAD_DIM + nt * 8 + 2 * c;
        *(__half2*)&Og[(size_t)(b * SS + r0g) * DIM + col] =
            __floats2half2_rn(o[nt][0] * inv0, o[nt][1] * inv0);
        *(__half2*)&Og[(size_t)(b * SS + r1g) * DIM + col] =
            __floats2half2_rn(o[nt][2] * inv1, o[nt][3] * inv1);
    }
}

// ---------------- launch ----------------
extern "C" void kernel_launch(void* const* d_in, const int* in_sizes, int n_in,
                              void* d_out, int out_size)
{
    const float* x    = (const float*)d_in[0];
    const float* fcos = (const float*)d_in[1];
    const float* fsin = (const float*)d_in[2];
    const float* wq   = (const float*)d_in[3];
    const float* wk   = (const float*)d_in[4];
    const float* wv   = (const float*)d_in[5];
    const float* wo   = (const float*)d_in[6];
    float* out = (float*)d_out;

    __half *xh, *wqkvh, *woh, *Qh, *Kh, *Vh, *Oh;
    cudaGetSymbolAddress((void**)&xh,    g_xh);
    cudaGetSymbolAddress((void**)&wqkvh, g_wqkv);
    cudaGetSymbolAddress((void**)&woh,   g_woh);
    cudaGetSymbolAddress((void**)&Qh,    g_Qh);
    cudaGetSymbolAddress((void**)&Kh,    g_Kh);
    cudaGetSymbolAddress((void**)&Vh,    g_Vh);
    cudaGetSymbolAddress((void**)&Oh,    g_Oh);

    // ---- conversions ----
    {
        int n = ROWS * DIM / 2;
        f2h<<<(n + 255) / 256, 256>>>(x, xh, n);
        int n2 = DIM * NQKV / 2;
        wcat<<<(n2 + 255) / 256, 256>>>(wq, wk, wv, wqkvh, n2);
        int n3 = DIM * DIM / 2;
        f2h<<<(n3 + 255) / 256, 256>>>(wo, woh, n3);
    }

    const int smem_gemm = 4 * (128 * 40 * 2 + 32 * 136 * 2);   // 75,776
    cudaFuncSetAttribute((const void*)hgemm<2>,
                         cudaFuncAttributeMaxDynamicSharedMemorySize, smem_gemm);
    cudaFuncSetAttribute((const void*)hgemm<0>,
                         cudaFuncAttributeMaxDynamicSharedMemorySize, smem_gemm);
    cudaFuncSetAttribute((const void*)flash_attn,
                         cudaFuncAttributeMaxDynamicSharedMemorySize, ATTN_SMEM);

    // ---- fused QKV projection + RoPE + fp16 store ----
    hgemm<2><<<dim3(NQKV / 128, ROWS / 128), 256, smem_gemm>>>(
        xh, wqkvh, nullptr, Qh, Kh, Vh, fcos, fsin, ROWS, NQKV, DIM);

    // ---- attention ----
    flash_attn<<<dim3(SS / 128, N_HEADS, BB), 256, ATTN_SMEM>>>(Qh, Kh, Vh, Oh);

    // ---- output projection (fp32 out) ----
    hgemm<0><<<dim3(DIM / 128, ROWS / 128), 256, smem_gemm>>>(
        Oh, woh, out, nullptr, nullptr, nullptr, nullptr, nullptr, ROWS, DIM, DIM);
}

// round 10
// speedup vs baseline: 12.1143x; 1.0250x over previous
#include <cuda_runtime.h>
#include <cuda_fp16.h>
#include <math_constants.h>
#include <cstdint>

#define DIM 2048
#define N_HEADS 16
#define N_KV_HEADS 4
#define HEAD_DIM 128
#define BB 2
#define SS 2048
#define ROWS (BB*SS)                  // 4096
#define KV_DIM (N_KV_HEADS*HEAD_DIM)  // 512
#define NQKV (DIM + 2*KV_DIM)         // 3072

// ---------------- static scratch (no allocations allowed) ----------------
__device__ __half g_xh  [(size_t)ROWS * DIM];
__device__ __half g_wqkv[(size_t)DIM * NQKV];
__device__ __half g_woh [(size_t)DIM * DIM];
__device__ __half g_Qh  [(size_t)ROWS * DIM];
__device__ __half g_Kh  [(size_t)ROWS * KV_DIM];
__device__ __half g_Vh  [(size_t)ROWS * KV_DIM];
__device__ __half g_Oh  [(size_t)ROWS * DIM];

// ---------------- low-level helpers ----------------
__device__ __forceinline__ uint32_t sptr(const void* p) {
    return (uint32_t)__cvta_generic_to_shared(p);
}
__device__ __forceinline__ void cp16(uint32_t dst, const void* src) {
    asm volatile("cp.async.cg.shared.global [%0], [%1], 16;\n" :: "r"(dst), "l"(src));
}
#define CP_COMMIT asm volatile("cp.async.commit_group;\n" ::: "memory")
#define CP_WAIT(N) asm volatile("cp.async.wait_group %0;\n" :: "n"(N) : "memory")

__device__ __forceinline__ void ldsm_x4(uint32_t* r, uint32_t a) {
    asm volatile("ldmatrix.sync.aligned.m8n8.x4.shared.b16 {%0,%1,%2,%3}, [%4];"
                 : "=r"(r[0]), "=r"(r[1]), "=r"(r[2]), "=r"(r[3]) : "r"(a));
}
__device__ __forceinline__ void ldsm_x4t(uint32_t* r, uint32_t a) {
    asm volatile("ldmatrix.sync.aligned.m8n8.x4.trans.shared.b16 {%0,%1,%2,%3}, [%4];"
                 : "=r"(r[0]), "=r"(r[1]), "=r"(r[2]), "=r"(r[3]) : "r"(a));
}
__device__ __forceinline__ void mma_f16(float* d, const uint32_t* a, uint32_t b0, uint32_t b1) {
    asm volatile(
        "mma.sync.aligned.m16n8k16.row.col.f32.f16.f16.f32 "
        "{%0,%1,%2,%3}, {%4,%5,%6,%7}, {%8,%9}, {%0,%1,%2,%3};"
        : "+f"(d[0]), "+f"(d[1]), "+f"(d[2]), "+f"(d[3])
        : "r"(a[0]), "r"(a[1]), "r"(a[2]), "r"(a[3]), "r"(b0), "r"(b1));
}
// bit-reinterpret: pack two floats -> half2 -> u32 (no intrinsic exists for the cast)
__device__ __forceinline__ uint32_t pack_h2(float lo, float hi) {
    __half2 h = __floats2half2_rn(lo, hi);
    return *reinterpret_cast<uint32_t*>(&h);
}

// ---------------- fp32 -> fp16 convert ----------------
__global__ void f2h(const float* __restrict__ in, __half* __restrict__ out, int n2) {
    int i = blockIdx.x * blockDim.x + threadIdx.x;
    if (i < n2) {
        float2 v = ((const float2*)in)[i];
        ((__half2*)out)[i] = __floats2half2_rn(v.x, v.y);
    }
}

// ---------------- concat wq|wk|wv -> fp16 [DIM][3072] ----------------
__global__ void wcat(const float* __restrict__ wq, const float* __restrict__ wk,
                     const float* __restrict__ wv, __half* __restrict__ out, int total2)
{
    int i = blockIdx.x * blockDim.x + threadIdx.x;
    if (i >= total2) return;
    int j = i * 2;
    int k = j / NQKV, n = j % NQKV;
    float2 v;
    if (n < DIM)                 v = *(const float2*)&wq[(size_t)k * DIM + n];
    else if (n < DIM + KV_DIM)   v = *(const float2*)&wk[(size_t)k * KV_DIM + (n - DIM)];
    else                         v = *(const float2*)&wv[(size_t)k * KV_DIM + (n - DIM - KV_DIM)];
    ((__half2*)out)[i] = __floats2half2_rn(v.x, v.y);
}

// ---------------- fp16 GEMM: 128x128x32, 4-stage, 2 CTAs/SM --------------
// C[M,N] = A[M,K] * B[K,N]. EPI: 0 = fp32 C, 2 = fused QKV split + RoPE.
template<int EPI>
__global__ __launch_bounds__(256, 2) void hgemm(
    const __half* __restrict__ A, const __half* __restrict__ B,
    float* __restrict__ C,
    __half* __restrict__ qout, __half* __restrict__ kout, __half* __restrict__ vout,
    const float* __restrict__ cosb, const float* __restrict__ sinb,
    int M, int N, int K)
{
    constexpr int BM = 128, BN = 128, BK = 32, STG = 4;
    constexpr int ASTR = BK + 8;           // 40 halves
    constexpr int BSTR = BN + 8;           // 136 halves
    constexpr int ASZB = BM * ASTR * 2;
    constexpr int BSZB = BK * BSTR * 2;
    constexpr int NNI  = 4;
    constexpr int CPB  = BN / 8;

    extern __shared__ char smem[];
    const uint32_t sA = sptr(smem);
    const uint32_t sB = sA + STG * ASZB;

    const int tid = threadIdx.x, warp = tid >> 5, lane = tid & 31;
    const int g = lane >> 2, c = lane & 3;
    const int wm = (warp & 1) * 64, wn = (warp >> 1) * 32;
    const int bm = blockIdx.y * BM, bn = blockIdx.x * BN;

    auto issue = [&](int kt) {
        const int st = kt & (STG - 1);
        const uint32_t da = sA + st * ASZB;
        const __half* ga = A + (size_t)bm * K + (size_t)kt * BK;
        #pragma unroll
        for (int i = tid; i < 128 * 4; i += 256) {
            int r = i >> 2, ch = i & 3;
            cp16(da + (r * ASTR + ch * 8) * 2, ga + (size_t)r * K + ch * 8);
        }
        const uint32_t db = sB + st * BSZB;
        const __half* gb = B + (size_t)kt * BK * N + bn;
        #pragma unroll
        for (int i = tid; i < 32 * CPB; i += 256) {
            int r = i / CPB, ch = i % CPB;
            cp16(db + (r * BSTR + ch * 8) * 2, gb + (size_t)r * N + ch * 8);
        }
    };

    issue(0); CP_COMMIT;
    issue(1); CP_COMMIT;
    issue(2); CP_COMMIT;

    float acc[4][NNI][4];
    #pragma unroll
    for (int mi = 0; mi < 4; mi++)
        #pragma unroll
        for (int ni = 0; ni < NNI; ni++)
            #pragma unroll
            for (int r = 0; r < 4; r++) acc[mi][ni][r] = 0.f;

    const uint32_t aBase = sA + (((wm + (lane & 15)) * ASTR) + ((lane >> 4) << 3)) * 2;
    const uint32_t bBase = sB + (((((lane >> 3) & 1) * 8 + (lane & 7)) * BSTR)
                                 + wn + ((lane >> 4) << 3)) * 2;

    const int NT = K / BK;
    for (int kt = 0; kt < NT; kt++) {
        CP_WAIT(2);
        __syncthreads();
        if (kt + 3 < NT) issue(kt + 3);
        CP_COMMIT;

        const int st = kt & (STG - 1);
        const uint32_t ab = aBase + st * ASZB;
        const uint32_t bb = bBase + st * BSZB;

        #pragma unroll
        for (int kk = 0; kk < 2; kk++) {
            const int kb = kk * 16;
            uint32_t af[4][4];
            #pragma unroll
            for (int mi = 0; mi < 4; mi++)
                ldsm_x4(af[mi], ab + (mi * 16 * ASTR + kb) * 2);
            uint32_t bf[NNI][2];
            #pragma unroll
            for (int nip = 0; nip < NNI / 2; nip++) {
                uint32_t t[4];
                ldsm_x4t(t, bb + (kb * BSTR + nip * 16) * 2);
                bf[2 * nip][0] = t[0]; bf[2 * nip][1] = t[1];
                bf[2 * nip + 1][0] = t[2]; bf[2 * nip + 1][1] = t[3];
            }
            #pragma unroll
            for (int mi = 0; mi < 4; mi++)
                #pragma unroll
                for (int ni = 0; ni < NNI; ni++)
                    mma_f16(acc[mi][ni], af[mi], bf[ni][0], bf[ni][1]);
        }
    }

    // ---- epilogue ----
    #pragma unroll
    for (int mi = 0; mi < 4; mi++) {
        const int r0 = bm + wm + mi * 16 + g;
        const int r1 = r0 + 8;
        #pragma unroll
        for (int ni = 0; ni < NNI; ni++) {
            const int col = bn + wn + ni * 8 + 2 * c;
            float v0 = acc[mi][ni][0], v1 = acc[mi][ni][1];
            float v2 = acc[mi][ni][2], v3 = acc[mi][ni][3];
            if (EPI == 0) {
                *(float2*)&C[(size_t)r0 * N + col] = make_float2(v0, v1);
                *(float2*)&C[(size_t)r1 * N + col] = make_float2(v2, v3);
            } else {
                const int s0 = r0 & (SS - 1), s1 = r1 & (SS - 1);
                if (col < DIM) {                      // Q + RoPE
                    const int d2 = (col & 127) >> 1;
                    float c0 = cosb[s0 * 64 + d2], n0 = sinb[s0 * 64 + d2];
                    float c1 = cosb[s1 * 64 + d2], n1 = sinb[s1 * 64 + d2];
                    *(__half2*)&qout[(size_t)r0 * DIM + col] =
                        __floats2half2_rn(v0 * c0 - v1 * n0, v0 * n0 + v1 * c0);
                    *(__half2*)&qout[(size_t)r1 * DIM + col] =
                        __floats2half2_rn(v2 * c1 - v3 * n1, v2 * n1 + v3 * c1);
                } else if (col < DIM + KV_DIM) {      // K + RoPE
                    const int cc = col - DIM;
                    const int d2 = (cc & 127) >> 1;
                    float c0 = cosb[s0 * 64 + d2], n0 = sinb[s0 * 64 + d2];
                    float c1 = cosb[s1 * 64 + d2], n1 = sinb[s1 * 64 + d2];
                    *(__half2*)&kout[(size_t)r0 * KV_DIM + cc] =
                        __floats2half2_rn(v0 * c0 - v1 * n0, v0 * n0 + v1 * c0);
                    *(__half2*)&kout[(size_t)r1 * KV_DIM + cc] =
                        __floats2half2_rn(v2 * c1 - v3 * n1, v2 * n1 + v3 * c1);
                } else {                              // V
                    const int cc = col - DIM - KV_DIM;
                    *(__half2*)&vout[(size_t)r0 * KV_DIM + cc] = __floats2half2_rn(v0, v1);
                    *(__half2*)&vout[(size_t)r1 * KV_DIM + cc] = __floats2half2_rn(v2, v3);
                }
            }
        }
    }
}

// ---------------- FlashAttention fp16, 3-stage cp.async K/V -------------
// P never touches smem: QK accumulators are repacked in registers into the
// PV mma A-fragment layout (identical __floats2half2_rn rounding as before).
#define KT   32
#define QSTR 136
#define KSTR 136
#define VSTR 136
#define KSTGB (KT*KSTR*2)
#define VSTGB (KT*VSTR*2)
#define ATTN_SMEM ((128*QSTR + 3*KT*KSTR + 3*KT*VSTR) * 2)

__global__ __launch_bounds__(256, 2) void flash_attn(
    const __half* __restrict__ Qg, const __half* __restrict__ Kg,
    const __half* __restrict__ Vg, __half* __restrict__ Og)
{
    extern __shared__ char smem[];
    __half* shQ = (__half*)smem;
    __half* shK = shQ + 128 * QSTR;
    __half* shV = shK + 3 * KT * KSTR;
    const uint32_t sQ = sptr(shQ), sK = sptr(shK), sV = sptr(shV);

    // heavy (large-qt) blocks first: causal work grows with qt
    const int qt = gridDim.x - 1 - blockIdx.x;
    const int h = blockIdx.y, b = blockIdx.z;
    const int kh = h >> 2;
    const int tid = threadIdx.x;
    const int warp = tid >> 5, lane = tid & 31;
    const int g = lane >> 2, c = lane & 3;
    const int wrow = warp * 16;
    const float scale = 0.08838834764831845f;

    const int nkt = (qt + 1) * 4;

    {
        const __half* gq = Qg + ((size_t)(b * SS + qt * 128) * N_HEADS + h) * HEAD_DIM;
        #pragma unroll
        for (int i = tid; i < 128 * 16; i += 256) {
            int r = i >> 4, ch = i & 15;
            cp16(sQ + (r * QSTR + ch * 8) * 2, gq + (size_t)r * N_HEADS * HEAD_DIM + ch * 8);
        }
    }
    auto kv_issue = [&](int s) {
        const int buf = s % 3;
        const __half* gk = Kg + ((size_t)(b * SS + s * KT) * N_KV_HEADS + kh) * HEAD_DIM;
        const __half* gv = Vg + ((size_t)(b * SS + s * KT) * N_KV_HEADS + kh) * HEAD_DIM;
        #pragma unroll
        for (int i = tid; i < KT * 16; i += 256) {
            int r = i >> 4, ch = i & 15;
            size_t off = (size_t)r * N_KV_HEADS * HEAD_DIM + ch * 8;
            cp16(sK + buf * KSTGB + (r * KSTR + ch * 8) * 2, gk + off);
            cp16(sV + buf * VSTGB + (r * VSTR + ch * 8) * 2, gv + off);
        }
    };
    kv_issue(0); CP_COMMIT;
    if (nkt > 1) kv_issue(1);
    CP_COMMIT;

    float o[16][4];
    #pragma unroll
    for (int nt = 0; nt < 16; nt++)
        #pragma unroll
        for (int r = 0; r < 4; r++) o[nt][r] = 0.f;

    float m0 = -CUDART_INF_F, m1 = -CUDART_INF_F, l0 = 0.f, l1 = 0.f;
    const int r0g = qt * 128 + wrow + g;
    const int r1g = r0g + 8;

    const uint32_t qB = sQ + (((wrow + (lane & 15)) * QSTR) + ((lane >> 4) << 3)) * 2;
    const uint32_t kB0 = sK + (((((lane >> 4) << 3) + (lane & 7)) * KSTR)
                               + (((lane >> 3) & 1) << 3)) * 2;
    const uint32_t vB0 = sV + ((((((lane >> 3) & 1) << 3) + (lane & 7)) * VSTR)
                               + ((lane >> 4) << 3)) * 2;

    for (int jt = 0; jt < nkt; jt++) {
        CP_WAIT(1);
        __syncthreads();
        if (jt + 2 < nkt) kv_issue(jt + 2);
        CP_COMMIT;

        const int buf = jt % 3, t0 = jt * KT;
        const uint32_t kB = kB0 + buf * KSTGB;
        const uint32_t vB = vB0 + buf * VSTGB;

        // ---- S = Q K^T : 16 x 32 per warp ----
        float s4[4][4];
        #pragma unroll
        for (int ni = 0; ni < 4; ni++)
            #pragma unroll
            for (int r = 0; r < 4; r++) s4[ni][r] = 0.f;

        #pragma unroll
        for (int ks = 0; ks < 8; ks++) {
            const int kb = ks * 16;
            uint32_t qf[4];
            ldsm_x4(qf, qB + kb * 2);
            uint32_t kf[8];
            ldsm_x4(kf,     kB + kb * 2);
            ldsm_x4(kf + 4, kB + (16 * KSTR + kb) * 2);
            mma_f16(s4[0], qf, kf[0], kf[1]);
            mma_f16(s4[1], qf, kf[2], kf[3]);
            mma_f16(s4[2], qf, kf[4], kf[5]);
            mma_f16(s4[3], qf, kf[6], kf[7]);
        }

        #pragma unroll
        for (int ni = 0; ni < 4; ni++)
            #pragma unroll
            for (int r = 0; r < 4; r++) s4[ni][r] *= scale;

        if (jt >= nkt - 4) {   // diagonal blocks
            #pragma unroll
            for (int ni = 0; ni < 4; ni++) {
                int key0 = t0 + ni * 8 + 2 * c;
                if (key0 > r0g)     s4[ni][0] = -CUDART_INF_F;
                if (key0 + 1 > r0g) s4[ni][1] = -CUDART_INF_F;
                if (key0 > r1g)     s4[ni][2] = -CUDART_INF_F;
                if (key0 + 1 > r1g) s4[ni][3] = -CUDART_INF_F;
            }
        }

        // ---- online softmax ----
        float mx0 = -CUDART_INF_F, mx1 = -CUDART_INF_F;
        #pragma unroll
        for (int ni = 0; ni < 4; ni++) {
            mx0 = fmaxf(mx0, fmaxf(s4[ni][0], s4[ni][1]));
            mx1 = fmaxf(mx1, fmaxf(s4[ni][2], s4[ni][3]));
        }
        mx0 = fmaxf(mx0, __shfl_xor_sync(0xffffffffu, mx0, 1));
        mx0 = fmaxf(mx0, __shfl_xor_sync(0xffffffffu, mx0, 2));
        mx1 = fmaxf(mx1, __shfl_xor_sync(0xffffffffu, mx1, 1));
        mx1 = fmaxf(mx1, __shfl_xor_sync(0xffffffffu, mx1, 2));

        float mn0 = fmaxf(m0, mx0), mn1 = fmaxf(m1, mx1);
        float corr0 = __expf(m0 - mn0), corr1 = __expf(m1 - mn1);
        m0 = mn0; m1 = mn1;

        // exp + pack directly into PV A-fragments (no smem round-trip)
        uint32_t pr[4][2];
        float ps0 = 0.f, ps1 = 0.f;
        #pragma unroll
        for (int ni = 0; ni < 4; ni++) {
            float p0 = __expf(s4[ni][0] - mn0);
            float p1 = __expf(s4[ni][1] - mn0);
            float p2 = __expf(s4[ni][2] - mn1);
            float p3 = __expf(s4[ni][3] - mn1);
            ps0 += p0 + p1;
            ps1 += p2 + p3;
            pr[ni][0] = pack_h2(p0, p1);
            pr[ni][1] = pack_h2(p2, p3);
        }
        ps0 += __shfl_xor_sync(0xffffffffu, ps0, 1);
        ps0 += __shfl_xor_sync(0xffffffffu, ps0, 2);
        ps1 += __shfl_xor_sync(0xffffffffu, ps1, 1);
        ps1 += __shfl_xor_sync(0xffffffffu, ps1, 2);
        l0 = l0 * corr0 + ps0;
        l1 = l1 * corr1 + ps1;

        // rescale O only when the running max actually moved (warp-uniform)
        if (__any_sync(0xffffffffu, (corr0 != 1.f) | (corr1 != 1.f))) {
            #pragma unroll
            for (int nt = 0; nt < 16; nt++) {
                o[nt][0] *= corr0; o[nt][1] *= corr0;
                o[nt][2] *= corr1; o[nt][3] *= corr1;
            }
        }

        // ---- O += P V (A-fragments straight from registers) ----
        #pragma unroll
        for (int ks = 0; ks < 2; ks++) {
            uint32_t pf[4] = { pr[2 * ks][0], pr[2 * ks][1],
                               pr[2 * ks + 1][0], pr[2 * ks + 1][1] };
            const int kb = ks * 16;
            #pragma unroll
            for (int np = 0; np < 8; np++) {
                uint32_t vf[4];
                ldsm_x4t(vf, vB + (kb * VSTR + np * 16) * 2);
                mma_f16(o[2 * np],     pf, vf[0], vf[1]);
                mma_f16(o[2 * np + 1], pf, vf[2], vf[3]);
            }
        }
    }

    const float inv0 = 1.f / l0, inv1 = 1.f / l1;
    #pragma unroll
    for (int nt = 0; nt < 16; nt++) {
        int col = h * HEAD_DIM + nt * 8 + 2 * c;
        *(__half2*)&Og[(size_t)(b * SS + r0g) * DIM + col] =
            __floats2half2_rn(o[nt][0] * inv0, o[nt][1] * inv0);
        *(__half2*)&Og[(size_t)(b * SS + r1g) * DIM + col] =
            __floats2half2_rn(o[nt][2] * inv1, o[nt][3] * inv1);
    }
}

// ---------------- launch ----------------
extern "C" void kernel_launch(void* const* d_in, const int* in_sizes, int n_in,
                              void* d_out, int out_size)
{
    const float* x    = (const float*)d_in[0];
    const float* fcos = (const float*)d_in[1];
    const float* fsin = (const float*)d_in[2];
    const float* wq   = (const float*)d_in[3];
    const float* wk   = (const float*)d_in[4];
    const float* wv   = (const float*)d_in[5];
    const float* wo   = (const float*)d_in[6];
    float* out = (float*)d_out;

    __half *xh, *wqkvh, *woh, *Qh, *Kh, *Vh, *Oh;
    cudaGetSymbolAddress((void**)&xh,    g_xh);
    cudaGetSymbolAddress((void**)&wqkvh, g_wqkv);
    cudaGetSymbolAddress((void**)&woh,   g_woh);
    cudaGetSymbolAddress((void**)&Qh,    g_Qh);
    cudaGetSymbolAddress((void**)&Kh,    g_Kh);
    cudaGetSymbolAddress((void**)&Vh,    g_Vh);
    cudaGetSymbolAddress((void**)&Oh,    g_Oh);

    // ---- conversions ----
    {
        int n = ROWS * DIM / 2;
        f2h<<<(n + 255) / 256, 256>>>(x, xh, n);
        int n2 = DIM * NQKV / 2;
        wcat<<<(n2 + 255) / 256, 256>>>(wq, wk, wv, wqkvh, n2);
        int n3 = DIM * DIM / 2;
        f2h<<<(n3 + 255) / 256, 256>>>(wo, woh, n3);
    }

    const int smem_gemm = 4 * (128 * 40 * 2 + 32 * 136 * 2);   // 75,776
    cudaFuncSetAttribute((const void*)hgemm<2>,
                         cudaFuncAttributeMaxDynamicSharedMemorySize, smem_gemm);
    cudaFuncSetAttribute((const void*)hgemm<0>,
                         cudaFuncAttributeMaxDynamicSharedMemorySize, smem_gemm);
    cudaFuncSetAttribute((const void*)flash_attn,
                         cudaFuncAttributeMaxDynamicSharedMemorySize, ATTN_SMEM);

    // ---- fused QKV projection + RoPE + fp16 store ----
    hgemm<2><<<dim3(NQKV / 128, ROWS / 128), 256, smem_gemm>>>(
        xh, wqkvh, nullptr, Qh, Kh, Vh, fcos, fsin, ROWS, NQKV, DIM);

    // ---- attention ----
    flash_attn<<<dim3(SS / 128, N_HEADS, BB), 256, ATTN_SMEM>>>(Qh, Kh, Vh, Oh);

    // ---- output projection (fp32 out) ----
    hgemm<0><<<dim3(DIM / 128, ROWS / 128), 256, smem_gemm>>>(
        Oh, woh, out, nullptr, nullptr, nullptr, nullptr, nullptr, ROWS, DIM, DIM);
}